// round 10
// baseline (speedup 1.0000x reference)
#include <cuda_runtime.h>
#include <cuda_fp16.h>
#include <cstdint>
#include <math.h>

#define Bb 16
#define Nn 1024
#define Dd 1024
#define Hh 8
#define HDd 128
#define SCALE_F 0.08838834764831845f   // 1/sqrt(128)
#define SCALE2  (0.08838834764831845f * 1.4426950408889634f)
#define NEG_F  -1e30f

// ---------------- scratch (static; no allocation allowed) ----------------
__device__ __align__(16) __half g_x16 [Bb*Nn*Dd];     // fp16 copy of x
__device__ __align__(16) __half g_Wq16[Hh*Dd*HDd];
__device__ __align__(16) __half g_Wk16[Hh*Dd*HDd];
__device__ __align__(16) __half g_Wv16[Hh*Dd*HDd];
__device__ __align__(16) __half g_Wfc16[Dd*Dd];
__device__ __align__(16) __half g_Q[Bb*Hh*Nn*HDd];    // [B,H,N,HD]
__device__ __align__(16) __half g_K[Bb*Hh*Nn*HDd];
__device__ __align__(16) __half g_V[Bb*Hh*Nn*HDd];
__device__ __align__(16) __half g_O16[Bb*Nn*Dd];      // [B,N,D]

// ---------------- helpers ----------------
__device__ __forceinline__ uint32_t smaddr(const void* p) {
    return (uint32_t)__cvta_generic_to_shared(p);
}
__device__ __forceinline__ void ldsm4(uint32_t& r0, uint32_t& r1, uint32_t& r2, uint32_t& r3, uint32_t a) {
    asm volatile("ldmatrix.sync.aligned.m8n8.x4.shared.b16 {%0,%1,%2,%3}, [%4];"
                 : "=r"(r0), "=r"(r1), "=r"(r2), "=r"(r3) : "r"(a));
}
__device__ __forceinline__ void ldsm4t(uint32_t& r0, uint32_t& r1, uint32_t& r2, uint32_t& r3, uint32_t a) {
    asm volatile("ldmatrix.sync.aligned.m8n8.x4.trans.shared.b16 {%0,%1,%2,%3}, [%4];"
                 : "=r"(r0), "=r"(r1), "=r"(r2), "=r"(r3) : "r"(a));
}
__device__ __forceinline__ void mma16(float c[4], const uint32_t a[4], const uint32_t b[2]) {
    asm volatile(
        "mma.sync.aligned.m16n8k16.row.col.f32.f16.f16.f32 "
        "{%0,%1,%2,%3}, {%4,%5,%6,%7}, {%8,%9}, {%0,%1,%2,%3};"
        : "+f"(c[0]), "+f"(c[1]), "+f"(c[2]), "+f"(c[3])
        : "r"(a[0]), "r"(a[1]), "r"(a[2]), "r"(a[3]), "r"(b[0]), "r"(b[1]));
}
__device__ __forceinline__ uint32_t packh2(float a, float b) {
    __half2 h = __floats2half2_rn(a, b);
    return *(uint32_t*)&h;
}
__device__ __forceinline__ uint32_t ex2h2(uint32_t x) {
    uint32_t r;
    asm("ex2.approx.f16x2 %0, %1;" : "=r"(r) : "r"(x));
    return r;
}
__device__ __forceinline__ float ex2f(float x) {
    float r;
    asm("ex2.approx.f32 %0, %1;" : "=f"(r) : "f"(x));
    return r;
}

#define CP16(dst_sm, src_g) \
    asm volatile("cp.async.cg.shared.global [%0], [%1], 16;" :: "r"(dst_sm), "l"(src_g))
#define CP_COMMIT() asm volatile("cp.async.commit_group;")
#define CP_WAIT0()  asm volatile("cp.async.wait_group 0;")
#define CP_WAIT1()  asm volatile("cp.async.wait_group 1;")

// ============================================================
// Kernel 0: convert fp32 inputs to fp16 scratch
// ============================================================
#define CV_X  4194304           // float4 counts
#define CV_W  262144
__global__ __launch_bounds__(256) void convert_all(
    const float* __restrict__ x,  const float* __restrict__ Wq,
    const float* __restrict__ Wk, const float* __restrict__ Wv,
    const float* __restrict__ Wfc)
{
    const int total = CV_X + 4*CV_W;
    for (int i = blockIdx.x * blockDim.x + threadIdx.x; i < total; i += gridDim.x * blockDim.x) {
        const float* src; __half* dst; int off;
        if (i < CV_X)                 { src = x;   dst = g_x16;  off = i; }
        else if (i < CV_X + CV_W)     { src = Wq;  dst = g_Wq16; off = i - CV_X; }
        else if (i < CV_X + 2*CV_W)   { src = Wk;  dst = g_Wk16; off = i - CV_X - CV_W; }
        else if (i < CV_X + 3*CV_W)   { src = Wv;  dst = g_Wv16; off = i - CV_X - 2*CV_W; }
        else                          { src = Wfc; dst = g_Wfc16; off = i - CV_X - 3*CV_W; }
        float4 v = ((const float4*)src)[off];
        uint2 u;
        u.x = packh2(v.x, v.y);
        u.y = packh2(v.z, v.w);
        ((uint2*)dst)[off] = u;
    }
}

// ============================================================
// GEMM geometry: CTA tile 128x256, warp tile 64x64 (2m x 4n),
// k-chunk 64, 2-stage cp.async.  0.75 LDSM-wf per MMA.
// ============================================================
#define A_ST 9216     // 128 * 72 halves
#define B_ST 16896    // 64 * 264 halves
#define GEMM_SMEM ((2*(A_ST + B_ST)) * 2)   // 104448 B

// Mainloop: requires t, lane, wm(0..1), wn(0..3), acc[4][8][4],
// As, Bs base pointers, lambda load_stage(k0, st) committing one group.
#define GEMM_MAINLOOP()                                                                  \
    load_stage(0, 0);                                                                    \
    CP_COMMIT();                                                                         \
    const int rowA = (lane & 15) * 72 + ((lane >> 4) << 3);                              \
    const int rowB = (((lane >> 3) & 1) * 8 + (lane & 7)) * 264 + (lane >> 4) * 8;       \
    for (int s = 0; s < 16; s++) {                                                       \
        int cur = s & 1;                                                                 \
        if (s < 15) { load_stage((s + 1) * 64, cur ^ 1); CP_COMMIT(); CP_WAIT1(); }      \
        else        { CP_WAIT0(); }                                                      \
        __syncthreads();                                                                 \
        const __half* Ac = As + cur * A_ST + wm * 64 * 72;                               \
        const __half* Bc = Bs + cur * B_ST + wn * 64;                                    \
        _Pragma("unroll")                                                                \
        for (int ks = 0; ks < 4; ks++) {                                                 \
            int kk = ks * 16;                                                            \
            uint32_t a[4][4];                                                            \
            _Pragma("unroll")                                                            \
            for (int mt = 0; mt < 4; mt++)                                               \
                ldsm4(a[mt][0], a[mt][1], a[mt][2], a[mt][3],                            \
                      smaddr(Ac + mt * 16 * 72 + rowA + kk));                            \
            uint32_t bf[8][2];                                                           \
            _Pragma("unroll")                                                            \
            for (int nb = 0; nb < 4; nb++) {                                             \
                uint32_t r0, r1, r2, r3;                                                 \
                ldsm4t(r0, r1, r2, r3, smaddr(Bc + kk * 264 + rowB + nb * 16));          \
                bf[nb * 2][0] = r0; bf[nb * 2][1] = r1;                                  \
                bf[nb * 2 + 1][0] = r2; bf[nb * 2 + 1][1] = r3;                          \
            }                                                                            \
            _Pragma("unroll")                                                            \
            for (int mt = 0; mt < 4; mt++)                                               \
                _Pragma("unroll")                                                        \
                for (int nt = 0; nt < 8; nt++)                                           \
                    mma16(acc[mt][nt], a[mt], bf[nt]);                                   \
        }                                                                                \
        __syncthreads();                                                                 \
    }

// ============================================================
// Kernel 1: fused QKV projection (fp16 in, fp16 out)
// grid (128 m-tiles, 1, 12 = proj*4 + head-pair), block 256
// N = 256 spans heads {2j, 2j+1}
// ============================================================
__global__ __launch_bounds__(256, 1) void qkv_gemm(
    const float* __restrict__ bq, const float* __restrict__ bk, const float* __restrict__ bv)
{
    extern __shared__ __half sm[];
    __half* As = sm;                // [2][128][72]
    __half* Bs = sm + 2*A_ST;       // [2][64][264]

    const int z = blockIdx.z;
    const int p = z >> 2;
    const int j = z & 3;            // head pair: heads 2j, 2j+1
    const __half* W   = (p == 0 ? g_Wq16 : (p == 1 ? g_Wk16 : g_Wv16));
    const float* bias = (p == 0 ? bq : (p == 1 ? bk : bv));
    __half* Cout      = (p == 0 ? g_Q : (p == 1 ? g_K : g_V));

    const int m0   = blockIdx.x * 128;
    const int t    = threadIdx.x;
    const int lane = t & 31;
    const int warp = t >> 5;
    const int g    = lane >> 2;
    const int tg   = lane & 3;
    const int wm   = warp >> 2;   // 0..1
    const int wn   = warp & 3;    // 0..3

    float acc[4][8][4];
#pragma unroll
    for (int mt = 0; mt < 4; mt++)
#pragma unroll
        for (int nt = 0; nt < 8; nt++)
#pragma unroll
            for (int i = 0; i < 4; i++) acc[mt][nt][i] = 0.f;

    auto load_stage = [&](int k0, int st) {
        __half* Ad = As + st * A_ST;
        __half* Bd = Bs + st * B_ST;
#pragma unroll
        for (int pp = 0; pp < 4; pp++) {
            int idx = t + pp * 256;
            int r = idx >> 3, c = (idx & 7) * 8;
            CP16(smaddr(Ad + r * 72 + c), g_x16 + (size_t)(m0 + r) * Dd + k0 + c);
        }
#pragma unroll
        for (int pp = 0; pp < 8; pp++) {
            int idx = t + pp * 256;
            int r = idx >> 5, c = (idx & 31) * 8;     // c in [0,256)
            int hh = c >> 7;                           // 0/1 within pair
            CP16(smaddr(Bd + r * 264 + c),
                 W + ((size_t)(2 * j + hh) * Dd + k0 + r) * HDd + (c & 127));
        }
    };

    GEMM_MAINLOOP()

    // epilogue -> [B,H,N,HD] fp16 (+bias); warp's 64-col slab is in one head
    {
        const int h = 2 * j + (wn >> 1);
        const int e0 = (wn & 1) * 64;
        const float* bi = bias + h * HDd;
#pragma unroll
        for (int mt = 0; mt < 4; mt++) {
#pragma unroll
            for (int half = 0; half < 2; half++) {
                int r  = m0 + wm * 64 + mt * 16 + g + half * 8;
                int bb = r >> 10;
                int n  = r & 1023;
                __half* dst = Cout + (((size_t)(bb * Hh + h)) * Nn + n) * HDd;
#pragma unroll
                for (int nt = 0; nt < 8; nt++) {
                    int e = e0 + nt * 8 + 2 * tg;
                    *(half2*)(dst + e) = __floats2half2_rn(
                        acc[mt][nt][half * 2 + 0] + bi[e],
                        acc[mt][nt][half * 2 + 1] + bi[e + 1]);
                }
            }
        }
    }
}

// ============================================================
// Kernel 2: flash attention (unchanged from round 9)
// grid (8 q-tiles, 8 heads, 16 batch), block 256, 2 CTAs/SM
// ============================================================
#define Q_SZ  17408            // 128*136 halves
#define KV_ST 8704             // 64*136 halves
#define ATTN_SMEM_BYTES ((Q_SZ + 4*KV_ST)*2 + 2*64*4)

__global__ __launch_bounds__(256, 2) void attn_kernel(const int* __restrict__ x_mask)
{
    extern __shared__ __half sm[];
    __half* Qs = sm;                    // [128][136]
    __half* Ks = sm + Q_SZ;             // [2][64][136]
    __half* Vs = Ks + 2 * KV_ST;        // [2][64][136]
    int*    km = (int*)(Vs + 2 * KV_ST);// [2][64]

    const int qt = blockIdx.x, h = blockIdx.y, b = blockIdx.z;
    const int t    = threadIdx.x;
    const int lane = t & 31;
    const int warp = t >> 5;
    const int g    = lane >> 2;
    const int tg   = lane & 3;
    const size_t bh = ((size_t)b * Hh + h) * Nn;
    const int q0 = qt * 128;
    const int rA = warp * 16 + g;
    const int rB = rA + 8;

#pragma unroll
    for (int pp = 0; pp < 8; pp++) {
        int idx = t + pp * 256;
        int r = idx >> 4, c = (idx & 15) * 8;
        CP16(smaddr(Qs + r * 136 + c), g_Q + (bh + q0 + r) * HDd + c);
    }
    auto load_kv = [&](int kt, int st) {
        int k0 = kt * 64;
        __half* Kd = Ks + st * KV_ST;
        __half* Vd = Vs + st * KV_ST;
#pragma unroll
        for (int pp = 0; pp < 4; pp++) {
            int idx = t + pp * 256;
            int r = idx >> 4, c = (idx & 15) * 8;
            CP16(smaddr(Kd + r * 136 + c), g_K + (bh + k0 + r) * HDd + c);
            CP16(smaddr(Vd + r * 136 + c), g_V + (bh + k0 + r) * HDd + c);
        }
        if (t < 64) km[st * 64 + t] = x_mask[b * Nn + k0 + t];
    };
    load_kv(0, 0);
    CP_COMMIT();

    const int qmA = x_mask[b * Nn + q0 + rA];
    const int qmB = x_mask[b * Nn + q0 + rB];
    float mA = -INFINITY, mB = -INFINITY, lA = 0.f, lB = 0.f;

    float o[16][4];
#pragma unroll
    for (int jj = 0; jj < 16; jj++)
#pragma unroll
        for (int i = 0; i < 4; i++) o[jj][i] = 0.f;

    for (int kt = 0; kt < 16; kt++) {
        const int cur = kt & 1;
        if (kt < 15) { load_kv(kt + 1, cur ^ 1); CP_COMMIT(); CP_WAIT1(); }
        else         { CP_WAIT0(); }
        __syncthreads();

        const __half* Kst = Ks + cur * KV_ST;
        const __half* Vst = Vs + cur * KV_ST;
        const int*    kmc = km + cur * 64;

        float s[8][4];
#pragma unroll
        for (int nt = 0; nt < 8; nt++)
#pragma unroll
            for (int i = 0; i < 4; i++) s[nt][i] = 0.f;

#pragma unroll
        for (int ks = 0; ks < 8; ks++) {
            int kk = ks * 16;
            uint32_t a[4];
            ldsm4(a[0], a[1], a[2], a[3],
                  smaddr(Qs + (warp * 16 + (lane & 15)) * 136 + kk + ((lane >> 4) << 3)));
#pragma unroll
            for (int nb = 0; nb < 4; nb++) {
                int n0 = nb * 16;
                uint32_t r0, r1, r2, r3;
                ldsm4(r0, r1, r2, r3,
                      smaddr(Kst + (n0 + ((lane >> 4) << 3) + (lane & 7)) * 136 + kk + ((lane >> 3) & 1) * 8));
                uint32_t b0[2] = { r0, r1 }, b1[2] = { r2, r3 };
                mma16(s[nb * 2], a, b0);
                mma16(s[nb * 2 + 1], a, b1);
            }
        }

#pragma unroll
        for (int nt = 0; nt < 8; nt++) {
            int c0 = nt * 8 + 2 * tg;
            int k0m = kmc[c0], k1m = kmc[c0 + 1];
            s[nt][0] = (qmA & k0m) ? s[nt][0] * SCALE2 : NEG_F;
            s[nt][1] = (qmA & k1m) ? s[nt][1] * SCALE2 : NEG_F;
            s[nt][2] = (qmB & k0m) ? s[nt][2] * SCALE2 : NEG_F;
            s[nt][3] = (qmB & k1m) ? s[nt][3] * SCALE2 : NEG_F;
        }

        float tmA = s[0][0], tmB = s[0][2];
#pragma unroll
        for (int nt = 0; nt < 8; nt++) {
            tmA = fmaxf(tmA, fmaxf(s[nt][0], s[nt][1]));
            tmB = fmaxf(tmB, fmaxf(s[nt][2], s[nt][3]));
        }
        tmA = fmaxf(tmA, __shfl_xor_sync(0xffffffffu, tmA, 1));
        tmA = fmaxf(tmA, __shfl_xor_sync(0xffffffffu, tmA, 2));
        tmB = fmaxf(tmB, __shfl_xor_sync(0xffffffffu, tmB, 1));
        tmB = fmaxf(tmB, __shfl_xor_sync(0xffffffffu, tmB, 2));

        float mnA = fmaxf(mA, tmA), mnB = fmaxf(mB, tmB);
        float alA = ex2f(mA - mnA), alB = ex2f(mB - mnB);
        mA = mnA; mB = mnB;

        uint32_t pA[8], pB[8];
        float sumA = 0.f, sumB = 0.f;
#pragma unroll
        for (int nt = 0; nt < 8; nt++) {
            uint32_t hA = packh2(s[nt][0] - mnA, s[nt][1] - mnA);
            uint32_t hB = packh2(s[nt][2] - mnB, s[nt][3] - mnB);
            uint32_t eA = ex2h2(hA);
            uint32_t eB = ex2h2(hB);
            pA[nt] = eA;
            pB[nt] = eB;
            float2 fA = __half22float2(*(half2*)&eA);
            float2 fB = __half22float2(*(half2*)&eB);
            sumA += fA.x + fA.y;
            sumB += fB.x + fB.y;
        }
        sumA += __shfl_xor_sync(0xffffffffu, sumA, 1);
        sumA += __shfl_xor_sync(0xffffffffu, sumA, 2);
        sumB += __shfl_xor_sync(0xffffffffu, sumB, 1);
        sumB += __shfl_xor_sync(0xffffffffu, sumB, 2);
        lA = lA * alA + sumA;
        lB = lB * alB + sumB;

#pragma unroll
        for (int jj = 0; jj < 16; jj++) {
            o[jj][0] *= alA; o[jj][1] *= alA;
            o[jj][2] *= alB; o[jj][3] *= alB;
        }

#pragma unroll
        for (int i = 0; i < 4; i++) {
            uint32_t a[4] = { pA[2 * i], pB[2 * i], pA[2 * i + 1], pB[2 * i + 1] };
#pragma unroll
            for (int nb = 0; nb < 8; nb++) {
                int n0 = nb * 16;
                uint32_t r0, r1, r2, r3;
                ldsm4t(r0, r1, r2, r3,
                       smaddr(Vst + (i * 16 + ((lane >> 3) & 1) * 8 + (lane & 7)) * 136 + n0 + (lane >> 4) * 8));
                uint32_t b0[2] = { r0, r1 }, b1[2] = { r2, r3 };
                mma16(o[nb * 2], a, b0);
                mma16(o[nb * 2 + 1], a, b1);
            }
        }
        __syncthreads();
    }

    const float invA = 1.f / lA;
    const float invB = 1.f / lB;
    __half* dA = g_O16 + ((size_t)(b * Nn) + q0 + rA) * Dd + h * HDd;
    __half* dB = g_O16 + ((size_t)(b * Nn) + q0 + rB) * Dd + h * HDd;
#pragma unroll
    for (int jj = 0; jj < 16; jj++) {
        int c0 = jj * 8 + 2 * tg;
        *(half2*)(dA + c0) = __floats2half2_rn(o[jj][0] * invA, o[jj][1] * invA);
        *(half2*)(dB + c0) = __floats2half2_rn(o[jj][2] * invB, o[jj][3] * invB);
    }
}

// ============================================================
// Kernel 3: out = O16 @ Wfc16 + bfc (fp32 out)
// grid (128 m-tiles, 4 n-tiles of 256), block 256
// ============================================================
__global__ __launch_bounds__(256, 1) void fc_gemm(
    const float* __restrict__ bfc, float* __restrict__ out)
{
    extern __shared__ __half sm[];
    __half* As = sm;
    __half* Bs = sm + 2*A_ST;

    const int m0 = blockIdx.x * 128;
    const int n0 = blockIdx.y * 256;
    const int t    = threadIdx.x;
    const int lane = t & 31;
    const int warp = t >> 5;
    const int g    = lane >> 2;
    const int tg   = lane & 3;
    const int wm   = warp >> 2;   // 0..1
    const int wn   = warp & 3;    // 0..3

    float acc[4][8][4];
#pragma unroll
    for (int mt = 0; mt < 4; mt++)
#pragma unroll
        for (int nt = 0; nt < 8; nt++)
#pragma unroll
            for (int i = 0; i < 4; i++) acc[mt][nt][i] = 0.f;

    auto load_stage = [&](int k0, int st) {
        __half* Ad = As + st * A_ST;
        __half* Bd = Bs + st * B_ST;
#pragma unroll
        for (int pp = 0; pp < 4; pp++) {
            int idx = t + pp * 256;
            int r = idx >> 3, c = (idx & 7) * 8;
            CP16(smaddr(Ad + r * 72 + c), g_O16 + (size_t)(m0 + r) * Dd + k0 + c);
        }
#pragma unroll
        for (int pp = 0; pp < 8; pp++) {
            int idx = t + pp * 256;
            int r = idx >> 5, c = (idx & 31) * 8;
            CP16(smaddr(Bd + r * 264 + c), g_Wfc16 + (size_t)(k0 + r) * Dd + n0 + c);
        }
    };

    GEMM_MAINLOOP()

#pragma unroll
    for (int mt = 0; mt < 4; mt++) {
#pragma unroll
        for (int half = 0; half < 2; half++) {
            int r = m0 + wm * 64 + mt * 16 + g + half * 8;
            float* dst = out + (size_t)r * Dd + n0 + wn * 64;
            const float* bi = bfc + n0 + wn * 64;
#pragma unroll
            for (int nt = 0; nt < 8; nt++) {
                int cc = nt * 8 + 2 * tg;
                float2 v;
                v.x = acc[mt][nt][half * 2 + 0] + bi[cc];
                v.y = acc[mt][nt][half * 2 + 1] + bi[cc + 1];
                *(float2*)(dst + cc) = v;
            }
        }
    }
}

// ============================================================
extern "C" void kernel_launch(void* const* d_in, const int* in_sizes, int n_in,
                              void* d_out, int out_size)
{
    const float* x      = (const float*)d_in[0];
    const int*   x_mask = (const int*)  d_in[1];
    const float* Wq     = (const float*)d_in[2];
    const float* bq     = (const float*)d_in[3];
    const float* Wk     = (const float*)d_in[4];
    const float* bk     = (const float*)d_in[5];
    const float* Wv     = (const float*)d_in[6];
    const float* bv     = (const float*)d_in[7];
    const float* Wfc    = (const float*)d_in[8];
    const float* bfc    = (const float*)d_in[9];
    float* out = (float*)d_out;

    static bool attr_done = false;
    if (!attr_done) {
        cudaFuncSetAttribute(attn_kernel, cudaFuncAttributeMaxDynamicSharedMemorySize, ATTN_SMEM_BYTES);
        cudaFuncSetAttribute(qkv_gemm,    cudaFuncAttributeMaxDynamicSharedMemorySize, GEMM_SMEM);
        cudaFuncSetAttribute(fc_gemm,     cudaFuncAttributeMaxDynamicSharedMemorySize, GEMM_SMEM);
        attr_done = true;
    }

    convert_all<<<2048, 256>>>(x, Wq, Wk, Wv, Wfc);
    qkv_gemm<<<dim3(128, 1, 12), 256, GEMM_SMEM>>>(bq, bk, bv);
    attn_kernel<<<dim3(8, 8, 16), 256, ATTN_SMEM_BYTES>>>(x_mask);
    fc_gemm<<<dim3(128, 4, 1), 256, GEMM_SMEM>>>(bfc, out);
}

// round 11
// speedup vs baseline: 1.0584x; 1.0584x over previous
#include <cuda_runtime.h>
#include <cuda_fp16.h>
#include <cstdint>
#include <math.h>

#define Bb 16
#define Nn 1024
#define Dd 1024
#define Hh 8
#define HDd 128
#define SCALE_F 0.08838834764831845f   // 1/sqrt(128)
#define SCALE2  (0.08838834764831845f * 1.4426950408889634f)
#define NEG_F  -1e30f

// ---------------- scratch (static; no allocation allowed) ----------------
__device__ __align__(16) __half g_x16 [Bb*Nn*Dd];     // fp16 copy of x
__device__ __align__(16) __half g_Wq16[Hh*Dd*HDd];
__device__ __align__(16) __half g_Wk16[Hh*Dd*HDd];
__device__ __align__(16) __half g_Wv16[Hh*Dd*HDd];
__device__ __align__(16) __half g_Wfc16[Dd*Dd];
__device__ __align__(16) __half g_Q[Bb*Hh*Nn*HDd];    // [B,H,N,HD]
__device__ __align__(16) __half g_K[Bb*Hh*Nn*HDd];
__device__ __align__(16) __half g_V[Bb*Hh*Nn*HDd];
__device__ __align__(16) __half g_O16[Bb*Nn*Dd];      // [B,N,D]

// ---------------- helpers ----------------
__device__ __forceinline__ uint32_t smaddr(const void* p) {
    return (uint32_t)__cvta_generic_to_shared(p);
}
__device__ __forceinline__ void ldsm4(uint32_t& r0, uint32_t& r1, uint32_t& r2, uint32_t& r3, uint32_t a) {
    asm volatile("ldmatrix.sync.aligned.m8n8.x4.shared.b16 {%0,%1,%2,%3}, [%4];"
                 : "=r"(r0), "=r"(r1), "=r"(r2), "=r"(r3) : "r"(a));
}
__device__ __forceinline__ void ldsm4t(uint32_t& r0, uint32_t& r1, uint32_t& r2, uint32_t& r3, uint32_t a) {
    asm volatile("ldmatrix.sync.aligned.m8n8.x4.trans.shared.b16 {%0,%1,%2,%3}, [%4];"
                 : "=r"(r0), "=r"(r1), "=r"(r2), "=r"(r3) : "r"(a));
}
__device__ __forceinline__ void mma16(float c[4], const uint32_t a[4], const uint32_t b[2]) {
    asm volatile(
        "mma.sync.aligned.m16n8k16.row.col.f32.f16.f16.f32 "
        "{%0,%1,%2,%3}, {%4,%5,%6,%7}, {%8,%9}, {%0,%1,%2,%3};"
        : "+f"(c[0]), "+f"(c[1]), "+f"(c[2]), "+f"(c[3])
        : "r"(a[0]), "r"(a[1]), "r"(a[2]), "r"(a[3]), "r"(b[0]), "r"(b[1]));
}
__device__ __forceinline__ uint32_t packh2(float a, float b) {
    __half2 h = __floats2half2_rn(a, b);
    return *(uint32_t*)&h;
}
__device__ __forceinline__ uint32_t ex2h2(uint32_t x) {
    uint32_t r;
    asm("ex2.approx.f16x2 %0, %1;" : "=r"(r) : "r"(x));
    return r;
}
__device__ __forceinline__ float ex2f(float x) {
    float r;
    asm("ex2.approx.f32 %0, %1;" : "=f"(r) : "f"(x));
    return r;
}

#define CP16(dst_sm, src_g) \
    asm volatile("cp.async.cg.shared.global [%0], [%1], 16;" :: "r"(dst_sm), "l"(src_g))
#define CP_COMMIT() asm volatile("cp.async.commit_group;")
#define CP_WAIT0()  asm volatile("cp.async.wait_group 0;")
#define CP_WAIT1()  asm volatile("cp.async.wait_group 1;")

// ============================================================
// Kernel 0: convert fp32 inputs to fp16 scratch
// ============================================================
#define CV_X  4194304           // float4 counts
#define CV_W  262144
__global__ __launch_bounds__(256) void convert_all(
    const float* __restrict__ x,  const float* __restrict__ Wq,
    const float* __restrict__ Wk, const float* __restrict__ Wv,
    const float* __restrict__ Wfc)
{
    const int total = CV_X + 4*CV_W;
    for (int i = blockIdx.x * blockDim.x + threadIdx.x; i < total; i += gridDim.x * blockDim.x) {
        const float* src; __half* dst; int off;
        if (i < CV_X)                 { src = x;   dst = g_x16;  off = i; }
        else if (i < CV_X + CV_W)     { src = Wq;  dst = g_Wq16; off = i - CV_X; }
        else if (i < CV_X + 2*CV_W)   { src = Wk;  dst = g_Wk16; off = i - CV_X - CV_W; }
        else if (i < CV_X + 3*CV_W)   { src = Wv;  dst = g_Wv16; off = i - CV_X - 2*CV_W; }
        else                          { src = Wfc; dst = g_Wfc16; off = i - CV_X - 3*CV_W; }
        float4 v = ((const float4*)src)[off];
        uint2 u;
        u.x = packh2(v.x, v.y);
        u.y = packh2(v.z, v.w);
        ((uint2*)dst)[off] = u;
    }
}

// ============================================================
// GEMM geometry: CTA tile 128x64, warp tile 32x32 (4m x 2n),
// k-chunk 64, 2-stage cp.async, 3 CTAs/SM (24 warps, occ 75%).
// ============================================================
#define A_ST 9216     // 128 * 72 halves
#define B_ST 4608     // 64 * 72 halves
#define GEMM_SMEM ((2*(A_ST + B_ST)) * 2)   // 55296 B

// Requires: t, lane, wm(0..3), wn(0..1), acc[2][4][4], As, Bs,
// lambda load_stage(k0, st) (no commit inside).
#define GEMM_MAINLOOP()                                                                  \
    load_stage(0, 0);                                                                    \
    CP_COMMIT();                                                                         \
    const int rowA = (lane & 15) * 72 + ((lane >> 4) << 3);                              \
    const int rowBk = (((lane >> 3) & 1) * 8 + (lane & 7)) * 72 + (lane >> 4) * 8;       \
    for (int s = 0; s < 16; s++) {                                                       \
        int cur = s & 1;                                                                 \
        if (s < 15) { load_stage((s + 1) * 64, cur ^ 1); CP_COMMIT(); CP_WAIT1(); }      \
        else        { CP_WAIT0(); }                                                      \
        __syncthreads();                                                                 \
        const __half* Ac = As + cur * A_ST + wm * 32 * 72;                               \
        const __half* Bc = Bs + cur * B_ST + wn * 32;                                    \
        _Pragma("unroll")                                                                \
        for (int ks = 0; ks < 4; ks++) {                                                 \
            int kk = ks * 16;                                                            \
            uint32_t a[2][4];                                                            \
            _Pragma("unroll")                                                            \
            for (int mt = 0; mt < 2; mt++)                                               \
                ldsm4(a[mt][0], a[mt][1], a[mt][2], a[mt][3],                            \
                      smaddr(Ac + mt * 16 * 72 + rowA + kk));                            \
            uint32_t bf[4][2];                                                           \
            _Pragma("unroll")                                                            \
            for (int nb = 0; nb < 2; nb++) {                                             \
                uint32_t r0, r1, r2, r3;                                                 \
                ldsm4t(r0, r1, r2, r3, smaddr(Bc + kk * 72 + rowBk + nb * 16));          \
                bf[nb * 2][0] = r0; bf[nb * 2][1] = r1;                                  \
                bf[nb * 2 + 1][0] = r2; bf[nb * 2 + 1][1] = r3;                          \
            }                                                                            \
            _Pragma("unroll")                                                            \
            for (int mt = 0; mt < 2; mt++)                                               \
                _Pragma("unroll")                                                        \
                for (int nt = 0; nt < 4; nt++)                                           \
                    mma16(acc[mt][nt], a[mt], bf[nt]);                                   \
        }                                                                                \
        __syncthreads();                                                                 \
    }

// ============================================================
// Kernel 1: fused QKV projection (fp16 in, fp16 out)
// grid (128 m-tiles, 1, 48), block 256.
// z: p = z/16, r = z%16, head h = r>>1, e0 = (r&1)*64
// ============================================================
__global__ __launch_bounds__(256, 3) void qkv_gemm(
    const float* __restrict__ bq, const float* __restrict__ bk, const float* __restrict__ bv)
{
    extern __shared__ __half sm[];
    __half* As = sm;                // [2][128][72]
    __half* Bs = sm + 2*A_ST;       // [2][64][72]

    const int z = blockIdx.z;
    const int p = z >> 4;
    const int zr = z & 15;
    const int h  = zr >> 1;
    const int e0 = (zr & 1) * 64;
    const __half* W   = (p == 0 ? g_Wq16 : (p == 1 ? g_Wk16 : g_Wv16));
    const float* bias = (p == 0 ? bq : (p == 1 ? bk : bv)) + h * HDd;
    __half* Cout      = (p == 0 ? g_Q : (p == 1 ? g_K : g_V));

    const int m0   = blockIdx.x * 128;
    const int t    = threadIdx.x;
    const int lane = t & 31;
    const int warp = t >> 5;
    const int g    = lane >> 2;
    const int tg   = lane & 3;
    const int wm   = warp >> 1;   // 0..3
    const int wn   = warp & 1;    // 0..1

    float acc[2][4][4];
#pragma unroll
    for (int mt = 0; mt < 2; mt++)
#pragma unroll
        for (int nt = 0; nt < 4; nt++)
#pragma unroll
            for (int i = 0; i < 4; i++) acc[mt][nt][i] = 0.f;

    auto load_stage = [&](int k0, int st) {
        __half* Ad = As + st * A_ST;
        __half* Bd = Bs + st * B_ST;
#pragma unroll
        for (int pp = 0; pp < 4; pp++) {
            int idx = t + pp * 256;
            int r = idx >> 3, c = (idx & 7) * 8;
            CP16(smaddr(Ad + r * 72 + c), g_x16 + (size_t)(m0 + r) * Dd + k0 + c);
        }
#pragma unroll
        for (int pp = 0; pp < 2; pp++) {
            int idx = t + pp * 256;
            int r = idx >> 3, c = (idx & 7) * 8;
            CP16(smaddr(Bd + r * 72 + c),
                 W + ((size_t)h * Dd + k0 + r) * HDd + e0 + c);
        }
    };

    GEMM_MAINLOOP()

    // epilogue -> [B,H,N,HD] fp16 (+bias)
#pragma unroll
    for (int mt = 0; mt < 2; mt++) {
#pragma unroll
        for (int half = 0; half < 2; half++) {
            int r  = m0 + wm * 32 + mt * 16 + g + half * 8;
            int bb = r >> 10;
            int n  = r & 1023;
            __half* dst = Cout + (((size_t)(bb * Hh + h)) * Nn + n) * HDd;
#pragma unroll
            for (int nt = 0; nt < 4; nt++) {
                int e = e0 + wn * 32 + nt * 8 + 2 * tg;
                *(half2*)(dst + e) = __floats2half2_rn(
                    acc[mt][nt][half * 2 + 0] + bias[e],
                    acc[mt][nt][half * 2 + 1] + bias[e + 1]);
            }
        }
    }
}

// ============================================================
// Kernel 2: flash attention (round-9 version, unchanged)
// grid (8 q-tiles, 8 heads, 16 batch), block 256, 2 CTAs/SM
// ============================================================
#define Q_SZ  17408            // 128*136 halves
#define KV_ST 8704             // 64*136 halves
#define ATTN_SMEM_BYTES ((Q_SZ + 4*KV_ST)*2 + 2*64*4)

__global__ __launch_bounds__(256, 2) void attn_kernel(const int* __restrict__ x_mask)
{
    extern __shared__ __half sm[];
    __half* Qs = sm;                    // [128][136]
    __half* Ks = sm + Q_SZ;             // [2][64][136]
    __half* Vs = Ks + 2 * KV_ST;        // [2][64][136]
    int*    km = (int*)(Vs + 2 * KV_ST);// [2][64]

    const int qt = blockIdx.x, h = blockIdx.y, b = blockIdx.z;
    const int t    = threadIdx.x;
    const int lane = t & 31;
    const int warp = t >> 5;
    const int g    = lane >> 2;
    const int tg   = lane & 3;
    const size_t bh = ((size_t)b * Hh + h) * Nn;
    const int q0 = qt * 128;
    const int rA = warp * 16 + g;
    const int rB = rA + 8;

#pragma unroll
    for (int pp = 0; pp < 8; pp++) {
        int idx = t + pp * 256;
        int r = idx >> 4, c = (idx & 15) * 8;
        CP16(smaddr(Qs + r * 136 + c), g_Q + (bh + q0 + r) * HDd + c);
    }
    auto load_kv = [&](int kt, int st) {
        int k0 = kt * 64;
        __half* Kd = Ks + st * KV_ST;
        __half* Vd = Vs + st * KV_ST;
#pragma unroll
        for (int pp = 0; pp < 4; pp++) {
            int idx = t + pp * 256;
            int r = idx >> 4, c = (idx & 15) * 8;
            CP16(smaddr(Kd + r * 136 + c), g_K + (bh + k0 + r) * HDd + c);
            CP16(smaddr(Vd + r * 136 + c), g_V + (bh + k0 + r) * HDd + c);
        }
        if (t < 64) km[st * 64 + t] = x_mask[b * Nn + k0 + t];
    };
    load_kv(0, 0);
    CP_COMMIT();

    const int qmA = x_mask[b * Nn + q0 + rA];
    const int qmB = x_mask[b * Nn + q0 + rB];
    float mA = -INFINITY, mB = -INFINITY, lA = 0.f, lB = 0.f;

    float o[16][4];
#pragma unroll
    for (int jj = 0; jj < 16; jj++)
#pragma unroll
        for (int i = 0; i < 4; i++) o[jj][i] = 0.f;

    for (int kt = 0; kt < 16; kt++) {
        const int cur = kt & 1;
        if (kt < 15) { load_kv(kt + 1, cur ^ 1); CP_COMMIT(); CP_WAIT1(); }
        else         { CP_WAIT0(); }
        __syncthreads();

        const __half* Kst = Ks + cur * KV_ST;
        const __half* Vst = Vs + cur * KV_ST;
        const int*    kmc = km + cur * 64;

        float s[8][4];
#pragma unroll
        for (int nt = 0; nt < 8; nt++)
#pragma unroll
            for (int i = 0; i < 4; i++) s[nt][i] = 0.f;

#pragma unroll
        for (int ks = 0; ks < 8; ks++) {
            int kk = ks * 16;
            uint32_t a[4];
            ldsm4(a[0], a[1], a[2], a[3],
                  smaddr(Qs + (warp * 16 + (lane & 15)) * 136 + kk + ((lane >> 4) << 3)));
#pragma unroll
            for (int nb = 0; nb < 4; nb++) {
                int n0 = nb * 16;
                uint32_t r0, r1, r2, r3;
                ldsm4(r0, r1, r2, r3,
                      smaddr(Kst + (n0 + ((lane >> 4) << 3) + (lane & 7)) * 136 + kk + ((lane >> 3) & 1) * 8));
                uint32_t b0[2] = { r0, r1 }, b1[2] = { r2, r3 };
                mma16(s[nb * 2], a, b0);
                mma16(s[nb * 2 + 1], a, b1);
            }
        }

#pragma unroll
        for (int nt = 0; nt < 8; nt++) {
            int c0 = nt * 8 + 2 * tg;
            int k0m = kmc[c0], k1m = kmc[c0 + 1];
            s[nt][0] = (qmA & k0m) ? s[nt][0] * SCALE2 : NEG_F;
            s[nt][1] = (qmA & k1m) ? s[nt][1] * SCALE2 : NEG_F;
            s[nt][2] = (qmB & k0m) ? s[nt][2] * SCALE2 : NEG_F;
            s[nt][3] = (qmB & k1m) ? s[nt][3] * SCALE2 : NEG_F;
        }

        float tmA = s[0][0], tmB = s[0][2];
#pragma unroll
        for (int nt = 0; nt < 8; nt++) {
            tmA = fmaxf(tmA, fmaxf(s[nt][0], s[nt][1]));
            tmB = fmaxf(tmB, fmaxf(s[nt][2], s[nt][3]));
        }
        tmA = fmaxf(tmA, __shfl_xor_sync(0xffffffffu, tmA, 1));
        tmA = fmaxf(tmA, __shfl_xor_sync(0xffffffffu, tmA, 2));
        tmB = fmaxf(tmB, __shfl_xor_sync(0xffffffffu, tmB, 1));
        tmB = fmaxf(tmB, __shfl_xor_sync(0xffffffffu, tmB, 2));

        float mnA = fmaxf(mA, tmA), mnB = fmaxf(mB, tmB);
        float alA = ex2f(mA - mnA), alB = ex2f(mB - mnB);
        mA = mnA; mB = mnB;

        uint32_t pA[8], pB[8];
        float sumA = 0.f, sumB = 0.f;
#pragma unroll
        for (int nt = 0; nt < 8; nt++) {
            uint32_t hA = packh2(s[nt][0] - mnA, s[nt][1] - mnA);
            uint32_t hB = packh2(s[nt][2] - mnB, s[nt][3] - mnB);
            uint32_t eA = ex2h2(hA);
            uint32_t eB = ex2h2(hB);
            pA[nt] = eA;
            pB[nt] = eB;
            float2 fA = __half22float2(*(half2*)&eA);
            float2 fB = __half22float2(*(half2*)&eB);
            sumA += fA.x + fA.y;
            sumB += fB.x + fB.y;
        }
        sumA += __shfl_xor_sync(0xffffffffu, sumA, 1);
        sumA += __shfl_xor_sync(0xffffffffu, sumA, 2);
        sumB += __shfl_xor_sync(0xffffffffu, sumB, 1);
        sumB += __shfl_xor_sync(0xffffffffu, sumB, 2);
        lA = lA * alA + sumA;
        lB = lB * alB + sumB;

#pragma unroll
        for (int jj = 0; jj < 16; jj++) {
            o[jj][0] *= alA; o[jj][1] *= alA;
            o[jj][2] *= alB; o[jj][3] *= alB;
        }

#pragma unroll
        for (int i = 0; i < 4; i++) {
            uint32_t a[4] = { pA[2 * i], pB[2 * i], pA[2 * i + 1], pB[2 * i + 1] };
#pragma unroll
            for (int nb = 0; nb < 8; nb++) {
                int n0 = nb * 16;
                uint32_t r0, r1, r2, r3;
                ldsm4t(r0, r1, r2, r3,
                       smaddr(Vst + (i * 16 + ((lane >> 3) & 1) * 8 + (lane & 7)) * 136 + n0 + (lane >> 4) * 8));
                uint32_t b0[2] = { r0, r1 }, b1[2] = { r2, r3 };
                mma16(o[nb * 2], a, b0);
                mma16(o[nb * 2 + 1], a, b1);
            }
        }
        __syncthreads();
    }

    const float invA = 1.f / lA;
    const float invB = 1.f / lB;
    __half* dA = g_O16 + ((size_t)(b * Nn) + q0 + rA) * Dd + h * HDd;
    __half* dB = g_O16 + ((size_t)(b * Nn) + q0 + rB) * Dd + h * HDd;
#pragma unroll
    for (int jj = 0; jj < 16; jj++) {
        int c0 = jj * 8 + 2 * tg;
        *(half2*)(dA + c0) = __floats2half2_rn(o[jj][0] * invA, o[jj][1] * invA);
        *(half2*)(dB + c0) = __floats2half2_rn(o[jj][2] * invB, o[jj][3] * invB);
    }
}

// ============================================================
// Kernel 3: out = O16 @ Wfc16 + bfc (fp32 out)
// grid (128 m-tiles, 16 n-tiles of 64), block 256
// ============================================================
__global__ __launch_bounds__(256, 3) void fc_gemm(
    const float* __restrict__ bfc, float* __restrict__ out)
{
    extern __shared__ __half sm[];
    __half* As = sm;
    __half* Bs = sm + 2*A_ST;

    const int m0 = blockIdx.x * 128;
    const int n0 = blockIdx.y * 64;
    const int t    = threadIdx.x;
    const int lane = t & 31;
    const int warp = t >> 5;
    const int g    = lane >> 2;
    const int tg   = lane & 3;
    const int wm   = warp >> 1;   // 0..3
    const int wn   = warp & 1;    // 0..1

    float acc[2][4][4];
#pragma unroll
    for (int mt = 0; mt < 2; mt++)
#pragma unroll
        for (int nt = 0; nt < 4; nt++)
#pragma unroll
            for (int i = 0; i < 4; i++) acc[mt][nt][i] = 0.f;

    auto load_stage = [&](int k0, int st) {
        __half* Ad = As + st * A_ST;
        __half* Bd = Bs + st * B_ST;
#pragma unroll
        for (int pp = 0; pp < 4; pp++) {
            int idx = t + pp * 256;
            int r = idx >> 3, c = (idx & 7) * 8;
            CP16(smaddr(Ad + r * 72 + c), g_O16 + (size_t)(m0 + r) * Dd + k0 + c);
        }
#pragma unroll
        for (int pp = 0; pp < 2; pp++) {
            int idx = t + pp * 256;
            int r = idx >> 3, c = (idx & 7) * 8;
            CP16(smaddr(Bd + r * 72 + c), g_Wfc16 + (size_t)(k0 + r) * Dd + n0 + c);
        }
    };

    GEMM_MAINLOOP()

#pragma unroll
    for (int mt = 0; mt < 2; mt++) {
#pragma unroll
        for (int half = 0; half < 2; half++) {
            int r = m0 + wm * 32 + mt * 16 + g + half * 8;
            float* dst = out + (size_t)r * Dd + n0;
#pragma unroll
            for (int nt = 0; nt < 4; nt++) {
                int cc = wn * 32 + nt * 8 + 2 * tg;
                float2 v;
                v.x = acc[mt][nt][half * 2 + 0] + bfc[n0 + cc];
                v.y = acc[mt][nt][half * 2 + 1] + bfc[n0 + cc + 1];
                *(float2*)(dst + cc) = v;
            }
        }
    }
}

// ============================================================
extern "C" void kernel_launch(void* const* d_in, const int* in_sizes, int n_in,
                              void* d_out, int out_size)
{
    const float* x      = (const float*)d_in[0];
    const int*   x_mask = (const int*)  d_in[1];
    const float* Wq     = (const float*)d_in[2];
    const float* bq     = (const float*)d_in[3];
    const float* Wk     = (const float*)d_in[4];
    const float* bk     = (const float*)d_in[5];
    const float* Wv     = (const float*)d_in[6];
    const float* bv     = (const float*)d_in[7];
    const float* Wfc    = (const float*)d_in[8];
    const float* bfc    = (const float*)d_in[9];
    float* out = (float*)d_out;

    static bool attr_done = false;
    if (!attr_done) {
        cudaFuncSetAttribute(attn_kernel, cudaFuncAttributeMaxDynamicSharedMemorySize, ATTN_SMEM_BYTES);
        cudaFuncSetAttribute(qkv_gemm,    cudaFuncAttributeMaxDynamicSharedMemorySize, GEMM_SMEM);
        cudaFuncSetAttribute(fc_gemm,     cudaFuncAttributeMaxDynamicSharedMemorySize, GEMM_SMEM);
        attr_done = true;
    }

    convert_all<<<2048, 256>>>(x, Wq, Wk, Wv, Wfc);
    qkv_gemm<<<dim3(128, 1, 48), 256, GEMM_SMEM>>>(bq, bk, bv);
    attn_kernel<<<dim3(8, 8, 16), 256, ATTN_SMEM_BYTES>>>(x_mask);
    fc_gemm<<<dim3(128, 16, 1), 256, GEMM_SMEM>>>(bfc, out);
}

// round 14
// speedup vs baseline: 1.1132x; 1.0518x over previous
#include <cuda_runtime.h>
#include <cuda_fp16.h>
#include <cstdint>
#include <math.h>

#define Bb 16
#define Nn 1024
#define Dd 1024
#define Hh 8
#define HDd 128
#define SCALE_F 0.08838834764831845f   // 1/sqrt(128)
#define SCALE2  (0.08838834764831845f * 1.4426950408889634f)
#define NEG_F  -1e30f

// ---------------- scratch (static; no allocation allowed) ----------------
__device__ __align__(16) __half g_x16 [Bb*Nn*Dd];     // fp16 copy of x
__device__ __align__(16) __half g_Wq16[Hh*Dd*HDd];
__device__ __align__(16) __half g_Wk16[Hh*Dd*HDd];
__device__ __align__(16) __half g_Wv16[Hh*Dd*HDd];
__device__ __align__(16) __half g_Wfc16[Dd*Dd];
__device__ __align__(16) __half g_Q[Bb*Hh*Nn*HDd];    // [B,H,N,HD]
__device__ __align__(16) __half g_K[Bb*Hh*Nn*HDd];
__device__ __align__(16) __half g_V[Bb*Hh*Nn*HDd];
__device__ __align__(16) __half g_O16[Bb*Nn*Dd];      // [B,N,D]

// ---------------- helpers ----------------
__device__ __forceinline__ uint32_t smaddr(const void* p) {
    return (uint32_t)__cvta_generic_to_shared(p);
}
__device__ __forceinline__ void ldsm4(uint32_t& r0, uint32_t& r1, uint32_t& r2, uint32_t& r3, uint32_t a) {
    asm volatile("ldmatrix.sync.aligned.m8n8.x4.shared.b16 {%0,%1,%2,%3}, [%4];"
                 : "=r"(r0), "=r"(r1), "=r"(r2), "=r"(r3) : "r"(a));
}
__device__ __forceinline__ void ldsm4t(uint32_t& r0, uint32_t& r1, uint32_t& r2, uint32_t& r3, uint32_t a) {
    asm volatile("ldmatrix.sync.aligned.m8n8.x4.trans.shared.b16 {%0,%1,%2,%3}, [%4];"
                 : "=r"(r0), "=r"(r1), "=r"(r2), "=r"(r3) : "r"(a));
}
__device__ __forceinline__ void mma16(float c[4], const uint32_t a[4], const uint32_t b[2]) {
    asm volatile(
        "mma.sync.aligned.m16n8k16.row.col.f32.f16.f16.f32 "
        "{%0,%1,%2,%3}, {%4,%5,%6,%7}, {%8,%9}, {%0,%1,%2,%3};"
        : "+f"(c[0]), "+f"(c[1]), "+f"(c[2]), "+f"(c[3])
        : "r"(a[0]), "r"(a[1]), "r"(a[2]), "r"(a[3]), "r"(b[0]), "r"(b[1]));
}
__device__ __forceinline__ uint32_t packh2(float a, float b) {
    __half2 h = __floats2half2_rn(a, b);
    return *(uint32_t*)&h;
}
__device__ __forceinline__ uint32_t ex2h2(uint32_t x) {
    uint32_t r;
    asm("ex2.approx.f16x2 %0, %1;" : "=r"(r) : "r"(x));
    return r;
}
__device__ __forceinline__ float ex2f(float x) {
    float r;
    asm("ex2.approx.f32 %0, %1;" : "=f"(r) : "f"(x));
    return r;
}

#define CP16(dst_sm, src_g) \
    asm volatile("cp.async.cg.shared.global [%0], [%1], 16;" :: "r"(dst_sm), "l"(src_g))
#define CP_COMMIT() asm volatile("cp.async.commit_group;")
#define CP_WAIT0()  asm volatile("cp.async.wait_group 0;")
#define CP_WAIT1()  asm volatile("cp.async.wait_group 1;")

// ============================================================
// Kernel 0: convert fp32 inputs to fp16 scratch
// ============================================================
#define CV_X  4194304           // float4 counts
#define CV_W  262144
__global__ __launch_bounds__(256) void convert_all(
    const float* __restrict__ x,  const float* __restrict__ Wq,
    const float* __restrict__ Wk, const float* __restrict__ Wv,
    const float* __restrict__ Wfc)
{
    const int total = CV_X + 4*CV_W;
    for (int i = blockIdx.x * blockDim.x + threadIdx.x; i < total; i += gridDim.x * blockDim.x) {
        const float* src; __half* dst; int off;
        if (i < CV_X)                 { src = x;   dst = g_x16;  off = i; }
        else if (i < CV_X + CV_W)     { src = Wq;  dst = g_Wq16; off = i - CV_X; }
        else if (i < CV_X + 2*CV_W)   { src = Wk;  dst = g_Wk16; off = i - CV_X - CV_W; }
        else if (i < CV_X + 3*CV_W)   { src = Wv;  dst = g_Wv16; off = i - CV_X - 2*CV_W; }
        else                          { src = Wfc; dst = g_Wfc16; off = i - CV_X - 3*CV_W; }
        float4 v = ((const float4*)src)[off];
        uint2 u;
        u.x = packh2(v.x, v.y);
        u.y = packh2(v.z, v.w);
        ((uint2*)dst)[off] = u;
    }
}

// ============================================================
// GEMM smem geometry (shared by qkv & fc): 2-stage, k-depth 64
// CTA tile 128x128, warp tile 32x64 — the measured optimum of the
// LDSM/MMA-ratio vs occupancy trade curve (r9/r10/r11 bracket).
// ============================================================
#define A_ST 9216     // 128 * 72 halves
#define B_ST 8704     // 64 * 136 halves
#define GEMM_SMEM ((2*(A_ST + B_ST)) * 2)

// ============================================================
// Kernel 1: fused QKV projection (fp16 in, fp16 out)
// grid (128 m-tiles, 1, 24 = proj*8+head), block 256
// ============================================================
__global__ __launch_bounds__(256) void qkv_gemm(
    const float* __restrict__ bq, const float* __restrict__ bk, const float* __restrict__ bv)
{
    extern __shared__ __half sm[];
    __half* As = sm;                // [2][128][72]
    __half* Bs = sm + 2*A_ST;       // [2][64][136]

    const int z = blockIdx.z;
    const int p = z >> 3;
    const int h = z & 7;
    const __half* W   = (p == 0 ? g_Wq16 : (p == 1 ? g_Wk16 : g_Wv16)) + (size_t)h * Dd * HDd;
    const float* bias = (p == 0 ? bq : (p == 1 ? bk : bv)) + h * HDd;
    __half* Cout      = (p == 0 ? g_Q : (p == 1 ? g_K : g_V));

    const int m0   = blockIdx.x * 128;
    const int t    = threadIdx.x;
    const int lane = t & 31;
    const int warp = t >> 5;
    const int g    = lane >> 2;
    const int tg   = lane & 3;
    const int wm   = warp >> 1;
    const int wn   = warp & 1;

    float acc[2][8][4];
#pragma unroll
    for (int mt = 0; mt < 2; mt++)
#pragma unroll
        for (int nt = 0; nt < 8; nt++)
#pragma unroll
            for (int i = 0; i < 4; i++) acc[mt][nt][i] = 0.f;

    auto load_stage = [&](int k0, int st) {
        __half* Ad = As + st * A_ST;
        __half* Bd = Bs + st * B_ST;
#pragma unroll
        for (int pp = 0; pp < 4; pp++) {
            int idx = t + pp * 256;
            int r = idx >> 3, c = (idx & 7) * 8;
            CP16(smaddr(Ad + r * 72 + c), g_x16 + (size_t)(m0 + r) * Dd + k0 + c);
        }
#pragma unroll
        for (int pp = 0; pp < 4; pp++) {
            int idx = t + pp * 256;
            int r = idx >> 4, c = (idx & 15) * 8;
            CP16(smaddr(Bd + r * 136 + c), W + (size_t)(k0 + r) * HDd + c);
        }
    };

    load_stage(0, 0);
    CP_COMMIT();

    for (int s = 0; s < 16; s++) {
        int cur = s & 1;
        if (s < 15) { load_stage((s + 1) * 64, cur ^ 1); CP_COMMIT(); CP_WAIT1(); }
        else        { CP_WAIT0(); }
        __syncthreads();

        const __half* Ac = As + cur * A_ST;
        const __half* Bc = Bs + cur * B_ST;
#pragma unroll
        for (int ks = 0; ks < 4; ks++) {
            int kk = ks * 16;
            uint32_t a[2][4];
#pragma unroll
            for (int mt = 0; mt < 2; mt++)
                ldsm4(a[mt][0], a[mt][1], a[mt][2], a[mt][3],
                      smaddr(Ac + (wm * 32 + mt * 16 + (lane & 15)) * 72 + kk + ((lane >> 4) << 3)));
            uint32_t bf[8][2];
#pragma unroll
            for (int nb = 0; nb < 4; nb++) {
                int n0 = wn * 64 + nb * 16;
                uint32_t r0, r1, r2, r3;
                ldsm4t(r0, r1, r2, r3,
                       smaddr(Bc + (kk + ((lane >> 3) & 1) * 8 + (lane & 7)) * 136 + n0 + (lane >> 4) * 8));
                bf[nb * 2][0] = r0; bf[nb * 2][1] = r1;
                bf[nb * 2 + 1][0] = r2; bf[nb * 2 + 1][1] = r3;
            }
#pragma unroll
            for (int mt = 0; mt < 2; mt++)
#pragma unroll
                for (int nt = 0; nt < 8; nt++)
                    mma16(acc[mt][nt], a[mt], bf[nt]);
        }
        __syncthreads();
    }

    // epilogue -> [B,H,N,HD] fp16 (+bias)
#pragma unroll
    for (int mt = 0; mt < 2; mt++) {
#pragma unroll
        for (int half = 0; half < 2; half++) {
            int r  = m0 + wm * 32 + mt * 16 + g + half * 8;
            int bb = r >> 10;
            int n  = r & 1023;
            __half* dst = Cout + (((size_t)(bb * Hh + h)) * Nn + n) * HDd;
#pragma unroll
            for (int nt = 0; nt < 8; nt++) {
                int cc = wn * 64 + nt * 8 + 2 * tg;
                *(half2*)(dst + cc) = __floats2half2_rn(
                    acc[mt][nt][half * 2 + 0] + bias[cc],
                    acc[mt][nt][half * 2 + 1] + bias[cc + 1]);
            }
        }
    }
}

// ============================================================
// Kernel 2: flash attention, warp-private softmax in exp2 domain,
// P via ex2.approx.f16x2, warp-uniform skip of the O/l rescale
// when no row in the warp saw a new max (alpha == 1 exactly).
// grid (8 q-tiles, 8 heads, 16 batch), block 256, 2 CTAs/SM
// ============================================================
#define Q_SZ  17408            // 128*136 halves
#define KV_ST 8704             // 64*136 halves
#define ATTN_SMEM_BYTES ((Q_SZ + 4*KV_ST)*2 + 2*64*4)

__global__ __launch_bounds__(256, 2) void attn_kernel(const int* __restrict__ x_mask)
{
    extern __shared__ __half sm[];
    __half* Qs = sm;                    // [128][136]
    __half* Ks = sm + Q_SZ;             // [2][64][136]
    __half* Vs = Ks + 2 * KV_ST;        // [2][64][136]
    int*    km = (int*)(Vs + 2 * KV_ST);// [2][64]

    const int qt = blockIdx.x, h = blockIdx.y, b = blockIdx.z;
    const int t    = threadIdx.x;
    const int lane = t & 31;
    const int warp = t >> 5;
    const int g    = lane >> 2;
    const int tg   = lane & 3;
    const size_t bh = ((size_t)b * Hh + h) * Nn;
    const int q0 = qt * 128;
    const int rA = warp * 16 + g;
    const int rB = rA + 8;

#pragma unroll
    for (int pp = 0; pp < 8; pp++) {
        int idx = t + pp * 256;
        int r = idx >> 4, c = (idx & 15) * 8;
        CP16(smaddr(Qs + r * 136 + c), g_Q + (bh + q0 + r) * HDd + c);
    }
    auto load_kv = [&](int kt, int st) {
        int k0 = kt * 64;
        __half* Kd = Ks + st * KV_ST;
        __half* Vd = Vs + st * KV_ST;
#pragma unroll
        for (int pp = 0; pp < 4; pp++) {
            int idx = t + pp * 256;
            int r = idx >> 4, c = (idx & 15) * 8;
            CP16(smaddr(Kd + r * 136 + c), g_K + (bh + k0 + r) * HDd + c);
            CP16(smaddr(Vd + r * 136 + c), g_V + (bh + k0 + r) * HDd + c);
        }
        if (t < 64) km[st * 64 + t] = x_mask[b * Nn + k0 + t];
    };
    load_kv(0, 0);
    CP_COMMIT();

    const int qmA = x_mask[b * Nn + q0 + rA];
    const int qmB = x_mask[b * Nn + q0 + rB];
    float mA = -INFINITY, mB = -INFINITY, lA = 0.f, lB = 0.f;

    float o[16][4];
#pragma unroll
    for (int jj = 0; jj < 16; jj++)
#pragma unroll
        for (int i = 0; i < 4; i++) o[jj][i] = 0.f;

    for (int kt = 0; kt < 16; kt++) {
        const int cur = kt & 1;
        if (kt < 15) { load_kv(kt + 1, cur ^ 1); CP_COMMIT(); CP_WAIT1(); }
        else         { CP_WAIT0(); }
        __syncthreads();

        const __half* Kst = Ks + cur * KV_ST;
        const __half* Vst = Vs + cur * KV_ST;
        const int*    kmc = km + cur * 64;

        float s[8][4];
#pragma unroll
        for (int nt = 0; nt < 8; nt++)
#pragma unroll
            for (int i = 0; i < 4; i++) s[nt][i] = 0.f;

#pragma unroll
        for (int ks = 0; ks < 8; ks++) {
            int kk = ks * 16;
            uint32_t a[4];
            ldsm4(a[0], a[1], a[2], a[3],
                  smaddr(Qs + (warp * 16 + (lane & 15)) * 136 + kk + ((lane >> 4) << 3)));
#pragma unroll
            for (int nb = 0; nb < 4; nb++) {
                int n0 = nb * 16;
                uint32_t r0, r1, r2, r3;
                ldsm4(r0, r1, r2, r3,
                      smaddr(Kst + (n0 + ((lane >> 4) << 3) + (lane & 7)) * 136 + kk + ((lane >> 3) & 1) * 8));
                uint32_t b0[2] = { r0, r1 }, b1[2] = { r2, r3 };
                mma16(s[nb * 2], a, b0);
                mma16(s[nb * 2 + 1], a, b1);
            }
        }

#pragma unroll
        for (int nt = 0; nt < 8; nt++) {
            int c0 = nt * 8 + 2 * tg;
            int k0m = kmc[c0], k1m = kmc[c0 + 1];
            s[nt][0] = (qmA & k0m) ? s[nt][0] * SCALE2 : NEG_F;
            s[nt][1] = (qmA & k1m) ? s[nt][1] * SCALE2 : NEG_F;
            s[nt][2] = (qmB & k0m) ? s[nt][2] * SCALE2 : NEG_F;
            s[nt][3] = (qmB & k1m) ? s[nt][3] * SCALE2 : NEG_F;
        }

        float tmA = s[0][0], tmB = s[0][2];
#pragma unroll
        for (int nt = 0; nt < 8; nt++) {
            tmA = fmaxf(tmA, fmaxf(s[nt][0], s[nt][1]));
            tmB = fmaxf(tmB, fmaxf(s[nt][2], s[nt][3]));
        }
        tmA = fmaxf(tmA, __shfl_xor_sync(0xffffffffu, tmA, 1));
        tmA = fmaxf(tmA, __shfl_xor_sync(0xffffffffu, tmA, 2));
        tmB = fmaxf(tmB, __shfl_xor_sync(0xffffffffu, tmB, 1));
        tmB = fmaxf(tmB, __shfl_xor_sync(0xffffffffu, tmB, 2));

        // grows-only max: alpha == 1.0 exactly when no update this tile
        const bool updA = tmA > mA;
        const bool updB = tmB > mB;
        float mnA = updA ? tmA : mA;
        float mnB = updB ? tmB : mB;
        float alA = updA ? ex2f(mA - mnA) : 1.f;
        float alB = updB ? ex2f(mB - mnB) : 1.f;
        mA = mnA; mB = mnB;

        uint32_t pA[8], pB[8];
        float sumA = 0.f, sumB = 0.f;
#pragma unroll
        for (int nt = 0; nt < 8; nt++) {
            uint32_t hA = packh2(s[nt][0] - mnA, s[nt][1] - mnA);
            uint32_t hB = packh2(s[nt][2] - mnB, s[nt][3] - mnB);
            uint32_t eA = ex2h2(hA);
            uint32_t eB = ex2h2(hB);
            pA[nt] = eA;
            pB[nt] = eB;
            float2 fA = __half22float2(*(half2*)&eA);
            float2 fB = __half22float2(*(half2*)&eB);
            sumA += fA.x + fA.y;
            sumB += fB.x + fB.y;
        }
        sumA += __shfl_xor_sync(0xffffffffu, sumA, 1);
        sumA += __shfl_xor_sync(0xffffffffu, sumA, 2);
        sumB += __shfl_xor_sync(0xffffffffu, sumB, 1);
        sumB += __shfl_xor_sync(0xffffffffu, sumB, 2);
        lA = lA * alA + sumA;
        lB = lB * alB + sumB;

        // warp-uniform skip: rescale only if ANY lane had a max update
        if (__any_sync(0xffffffffu, updA | updB)) {
#pragma unroll
            for (int jj = 0; jj < 16; jj++) {
                o[jj][0] *= alA; o[jj][1] *= alA;
                o[jj][2] *= alB; o[jj][3] *= alB;
            }
        }

#pragma unroll
        for (int i = 0; i < 4; i++) {
            uint32_t a[4] = { pA[2 * i], pB[2 * i], pA[2 * i + 1], pB[2 * i + 1] };
#pragma unroll
            for (int nb = 0; nb < 8; nb++) {
                int n0 = nb * 16;
                uint32_t r0, r1, r2, r3;
                ldsm4t(r0, r1, r2, r3,
                       smaddr(Vst + (i * 16 + ((lane >> 3) & 1) * 8 + (lane & 7)) * 136 + n0 + (lane >> 4) * 8));
                uint32_t b0[2] = { r0, r1 }, b1[2] = { r2, r3 };
                mma16(o[nb * 2], a, b0);
                mma16(o[nb * 2 + 1], a, b1);
            }
        }
        __syncthreads();
    }

    const float invA = 1.f / lA;
    const float invB = 1.f / lB;
    __half* dA = g_O16 + ((size_t)(b * Nn) + q0 + rA) * Dd + h * HDd;
    __half* dB = g_O16 + ((size_t)(b * Nn) + q0 + rB) * Dd + h * HDd;
#pragma unroll
    for (int jj = 0; jj < 16; jj++) {
        int c0 = jj * 8 + 2 * tg;
        *(half2*)(dA + c0) = __floats2half2_rn(o[jj][0] * invA, o[jj][1] * invA);
        *(half2*)(dB + c0) = __floats2half2_rn(o[jj][2] * invB, o[jj][3] * invB);
    }
}

// ============================================================
// Kernel 3: out = O16 @ Wfc16 + bfc (fp32 out)
// grid (128 m-tiles, 8 n-tiles), block 256
// ============================================================
__global__ __launch_bounds__(256) void fc_gemm(
    const float* __restrict__ bfc, float* __restrict__ out)
{
    extern __shared__ __half sm[];
    __half* As = sm;
    __half* Bs = sm + 2*A_ST;

    const int m0 = blockIdx.x * 128;
    const int n0 = blockIdx.y * 128;
    const int t    = threadIdx.x;
    const int lane = t & 31;
    const int warp = t >> 5;
    const int g    = lane >> 2;
    const int tg   = lane & 3;
    const int wm   = warp >> 1;
    const int wn   = warp & 1;

    float acc[2][8][4];
#pragma unroll
    for (int mt = 0; mt < 2; mt++)
#pragma unroll
        for (int nt = 0; nt < 8; nt++)
#pragma unroll
            for (int i = 0; i < 4; i++) acc[mt][nt][i] = 0.f;

    auto load_stage = [&](int k0, int st) {
        __half* Ad = As + st * A_ST;
        __half* Bd = Bs + st * B_ST;
#pragma unroll
        for (int pp = 0; pp < 4; pp++) {
            int idx = t + pp * 256;
            int r = idx >> 3, c = (idx & 7) * 8;
            CP16(smaddr(Ad + r * 72 + c), g_O16 + (size_t)(m0 + r) * Dd + k0 + c);
        }
#pragma unroll
        for (int pp = 0; pp < 4; pp++) {
            int idx = t + pp * 256;
            int r = idx >> 4, c = (idx & 15) * 8;
            CP16(smaddr(Bd + r * 136 + c), g_Wfc16 + (size_t)(k0 + r) * Dd + n0 + c);
        }
    };

    load_stage(0, 0);
    CP_COMMIT();

    for (int s = 0; s < 16; s++) {
        int cur = s & 1;
        if (s < 15) { load_stage((s + 1) * 64, cur ^ 1); CP_COMMIT(); CP_WAIT1(); }
        else        { CP_WAIT0(); }
        __syncthreads();

        const __half* Ac = As + cur * A_ST;
        const __half* Bc = Bs + cur * B_ST;
#pragma unroll
        for (int ks = 0; ks < 4; ks++) {
            int kk = ks * 16;
            uint32_t a[2][4];
#pragma unroll
            for (int mt = 0; mt < 2; mt++)
                ldsm4(a[mt][0], a[mt][1], a[mt][2], a[mt][3],
                      smaddr(Ac + (wm * 32 + mt * 16 + (lane & 15)) * 72 + kk + ((lane >> 4) << 3)));
            uint32_t bf[8][2];
#pragma unroll
            for (int nb = 0; nb < 4; nb++) {
                int nn0 = wn * 64 + nb * 16;
                uint32_t r0, r1, r2, r3;
                ldsm4t(r0, r1, r2, r3,
                       smaddr(Bc + (kk + ((lane >> 3) & 1) * 8 + (lane & 7)) * 136 + nn0 + (lane >> 4) * 8));
                bf[nb * 2][0] = r0; bf[nb * 2][1] = r1;
                bf[nb * 2 + 1][0] = r2; bf[nb * 2 + 1][1] = r3;
            }
#pragma unroll
            for (int mt = 0; mt < 2; mt++)
#pragma unroll
                for (int nt = 0; nt < 8; nt++)
                    mma16(acc[mt][nt], a[mt], bf[nt]);
        }
        __syncthreads();
    }

#pragma unroll
    for (int mt = 0; mt < 2; mt++) {
#pragma unroll
        for (int half = 0; half < 2; half++) {
            int r = m0 + wm * 32 + mt * 16 + g + half * 8;
            float* dst = out + (size_t)r * Dd + n0;
#pragma unroll
            for (int nt = 0; nt < 8; nt++) {
                int cc = wn * 64 + nt * 8 + 2 * tg;
                float2 v;
                v.x = acc[mt][nt][half * 2 + 0] + bfc[n0 + cc];
                v.y = acc[mt][nt][half * 2 + 1] + bfc[n0 + cc + 1];
                *(float2*)(dst + cc) = v;
            }
        }
    }
}

// ============================================================
extern "C" void kernel_launch(void* const* d_in, const int* in_sizes, int n_in,
                              void* d_out, int out_size)
{
    const float* x      = (const float*)d_in[0];
    const int*   x_mask = (const int*)  d_in[1];
    const float* Wq     = (const float*)d_in[2];
    const float* bq     = (const float*)d_in[3];
    const float* Wk     = (const float*)d_in[4];
    const float* bk     = (const float*)d_in[5];
    const float* Wv     = (const float*)d_in[6];
    const float* bv     = (const float*)d_in[7];
    const float* Wfc    = (const float*)d_in[8];
    const float* bfc    = (const float*)d_in[9];
    float* out = (float*)d_out;

    static bool attr_done = false;
    if (!attr_done) {
        cudaFuncSetAttribute(attn_kernel, cudaFuncAttributeMaxDynamicSharedMemorySize, ATTN_SMEM_BYTES);
        cudaFuncSetAttribute(qkv_gemm,    cudaFuncAttributeMaxDynamicSharedMemorySize, GEMM_SMEM);
        cudaFuncSetAttribute(fc_gemm,     cudaFuncAttributeMaxDynamicSharedMemorySize, GEMM_SMEM);
        attr_done = true;
    }

    convert_all<<<2048, 256>>>(x, Wq, Wk, Wv, Wfc);
    qkv_gemm<<<dim3(128, 1, 24), 256, GEMM_SMEM>>>(bq, bk, bv);
    attn_kernel<<<dim3(8, 8, 16), 256, ATTN_SMEM_BYTES>>>(x_mask);
    fc_gemm<<<dim3(128, 8, 1), 256, GEMM_SMEM>>>(bfc, out);
}

// round 15
// speedup vs baseline: 1.3212x; 1.1868x over previous
#include <cuda_runtime.h>
#include <cuda_fp16.h>
#include <cstdint>
#include <math.h>

#define Bb 16
#define Nn 1024
#define Dd 1024
#define Hh 8
#define HDd 128
#define SCALE_F 0.08838834764831845f   // 1/sqrt(128)
#define SCALE2  (0.08838834764831845f * 1.4426950408889634f)
#define NEG_F  -1e30f

// ---------------- scratch (static; no allocation allowed) ----------------
__device__ __align__(16) __half g_x16 [Bb*Nn*Dd];     // fp16 copy of x
__device__ __align__(16) __half g_Wq16[Hh*Dd*HDd];
__device__ __align__(16) __half g_Wk16[Hh*Dd*HDd];
__device__ __align__(16) __half g_Wv16[Hh*Dd*HDd];
__device__ __align__(16) __half g_Wfc16[Dd*Dd];
__device__ __align__(16) __half g_Q[Bb*Hh*Nn*HDd];    // [B,H,N,HD]
__device__ __align__(16) __half g_K[Bb*Hh*Nn*HDd];
__device__ __align__(16) __half g_V[Bb*Hh*Nn*HDd];
__device__ __align__(16) __half g_O16[Bb*Nn*Dd];      // [B,N,D]
__device__ int   g_vidx[Bb*Nn];                       // per-batch compacted valid tokens
__device__ int   g_nv[Bb];                            // valid count per batch
__device__ float g_Vmean[Bb*Hh*HDd];                  // mean of V over all tokens

// ---------------- helpers ----------------
__device__ __forceinline__ uint32_t smaddr(const void* p) {
    return (uint32_t)__cvta_generic_to_shared(p);
}
__device__ __forceinline__ void ldsm4(uint32_t& r0, uint32_t& r1, uint32_t& r2, uint32_t& r3, uint32_t a) {
    asm volatile("ldmatrix.sync.aligned.m8n8.x4.shared.b16 {%0,%1,%2,%3}, [%4];"
                 : "=r"(r0), "=r"(r1), "=r"(r2), "=r"(r3) : "r"(a));
}
__device__ __forceinline__ void ldsm4t(uint32_t& r0, uint32_t& r1, uint32_t& r2, uint32_t& r3, uint32_t a) {
    asm volatile("ldmatrix.sync.aligned.m8n8.x4.trans.shared.b16 {%0,%1,%2,%3}, [%4];"
                 : "=r"(r0), "=r"(r1), "=r"(r2), "=r"(r3) : "r"(a));
}
__device__ __forceinline__ void mma16(float c[4], const uint32_t a[4], const uint32_t b[2]) {
    asm volatile(
        "mma.sync.aligned.m16n8k16.row.col.f32.f16.f16.f32 "
        "{%0,%1,%2,%3}, {%4,%5,%6,%7}, {%8,%9}, {%0,%1,%2,%3};"
        : "+f"(c[0]), "+f"(c[1]), "+f"(c[2]), "+f"(c[3])
        : "r"(a[0]), "r"(a[1]), "r"(a[2]), "r"(a[3]), "r"(b[0]), "r"(b[1]));
}
__device__ __forceinline__ uint32_t packh2(float a, float b) {
    __half2 h = __floats2half2_rn(a, b);
    return *(uint32_t*)&h;
}
__device__ __forceinline__ uint32_t ex2h2(uint32_t x) {
    uint32_t r;
    asm("ex2.approx.f16x2 %0, %1;" : "=r"(r) : "r"(x));
    return r;
}
__device__ __forceinline__ float ex2f(float x) {
    float r;
    asm("ex2.approx.f32 %0, %1;" : "=f"(r) : "f"(x));
    return r;
}

#define CP16(dst_sm, src_g) \
    asm volatile("cp.async.cg.shared.global [%0], [%1], 16;" :: "r"(dst_sm), "l"(src_g))
#define CP_COMMIT() asm volatile("cp.async.commit_group;")
#define CP_WAIT0()  asm volatile("cp.async.wait_group 0;")
#define CP_WAIT1()  asm volatile("cp.async.wait_group 1;")

// ============================================================
// Kernel 0: convert fp32 inputs to fp16 scratch
// ============================================================
#define CV_X  4194304           // float4 counts
#define CV_W  262144
__global__ __launch_bounds__(256) void convert_all(
    const float* __restrict__ x,  const float* __restrict__ Wq,
    const float* __restrict__ Wk, const float* __restrict__ Wv,
    const float* __restrict__ Wfc)
{
    const int total = CV_X + 4*CV_W;
    for (int i = blockIdx.x * blockDim.x + threadIdx.x; i < total; i += gridDim.x * blockDim.x) {
        const float* src; __half* dst; int off;
        if (i < CV_X)                 { src = x;   dst = g_x16;  off = i; }
        else if (i < CV_X + CV_W)     { src = Wq;  dst = g_Wq16; off = i - CV_X; }
        else if (i < CV_X + 2*CV_W)   { src = Wk;  dst = g_Wk16; off = i - CV_X - CV_W; }
        else if (i < CV_X + 3*CV_W)   { src = Wv;  dst = g_Wv16; off = i - CV_X - 2*CV_W; }
        else                          { src = Wfc; dst = g_Wfc16; off = i - CV_X - 3*CV_W; }
        float4 v = ((const float4*)src)[off];
        uint2 u;
        u.x = packh2(v.x, v.y);
        u.y = packh2(v.z, v.w);
        ((uint2*)dst)[off] = u;
    }
}

// ============================================================
// Kernel 0b: per-batch compaction of valid token indices
// grid (16), block 1024
// ============================================================
__global__ __launch_bounds__(1024) void build_valid(const int* __restrict__ x_mask)
{
    __shared__ int pre[1024];
    const int b = blockIdx.x, t = threadIdx.x;
    const int m = x_mask[b * Nn + t];
    pre[t] = m;
    __syncthreads();
    for (int off = 1; off < 1024; off <<= 1) {
        int v = (t >= off) ? pre[t - off] : 0;
        __syncthreads();
        pre[t] += v;
        __syncthreads();
    }
    if (m) g_vidx[b * Nn + pre[t] - 1] = t;
    if (t == 1023) g_nv[b] = pre[1023];
}

// ============================================================
// Kernel 0c: Vmean[b][h][e] = (1/1024) sum_n V[b][h][n][e]
// grid (8, 16), block 128
// ============================================================
__global__ __launch_bounds__(128) void vsum_kernel()
{
    const int h = blockIdx.x, b = blockIdx.y, e = threadIdx.x;
    const __half* V = g_V + ((size_t)(b * Hh + h) * Nn) * HDd + e;
    float s0 = 0.f, s1 = 0.f, s2 = 0.f, s3 = 0.f;
    for (int n = 0; n < Nn; n += 4) {
        s0 += __half2float(V[(size_t)(n + 0) * HDd]);
        s1 += __half2float(V[(size_t)(n + 1) * HDd]);
        s2 += __half2float(V[(size_t)(n + 2) * HDd]);
        s3 += __half2float(V[(size_t)(n + 3) * HDd]);
    }
    g_Vmean[(b * Hh + h) * HDd + e] = (s0 + s1 + s2 + s3) * (1.f / 1024.f);
}

// ============================================================
// Kernel 0d: masked q rows get o = Vmean (uniform softmax over all keys)
// grid (512, 16), block 256: w = tok*128 + h*16 + chunk
// ============================================================
__global__ __launch_bounds__(256) void fill_invalid(const int* __restrict__ x_mask)
{
    const int b = blockIdx.y;
    const int w = blockIdx.x * 256 + threadIdx.x;  // 0..131071
    const int tok = w >> 7;
    const int rem = w & 127;
    const int h   = rem >> 4;
    const int cc  = (rem & 15) * 8;
    if (x_mask[b * Nn + tok]) return;
    const float* vm = g_Vmean + (b * Hh + h) * HDd + cc;
    __half* dst = g_O16 + ((size_t)(b * Nn) + tok) * Dd + h * HDd + cc;
    uint4 u;
    u.x = packh2(vm[0], vm[1]);
    u.y = packh2(vm[2], vm[3]);
    u.z = packh2(vm[4], vm[5]);
    u.w = packh2(vm[6], vm[7]);
    *(uint4*)dst = u;
}

// ============================================================
// GEMM smem geometry (shared by qkv & fc): 2-stage, k-depth 64
// CTA tile 128x128, warp tile 32x64 (the measured optimum).
// ============================================================
#define A_ST 9216     // 128 * 72 halves
#define B_ST 8704     // 64 * 136 halves
#define GEMM_SMEM ((2*(A_ST + B_ST)) * 2)

// ============================================================
// Kernel 1: fused QKV projection (fp16 in, fp16 out)
// grid (128 m-tiles, 1, 24 = proj*8+head), block 256
// ============================================================
__global__ __launch_bounds__(256) void qkv_gemm(
    const float* __restrict__ bq, const float* __restrict__ bk, const float* __restrict__ bv)
{
    extern __shared__ __half sm[];
    __half* As = sm;                // [2][128][72]
    __half* Bs = sm + 2*A_ST;       // [2][64][136]

    const int z = blockIdx.z;
    const int p = z >> 3;
    const int h = z & 7;
    const __half* W   = (p == 0 ? g_Wq16 : (p == 1 ? g_Wk16 : g_Wv16)) + (size_t)h * Dd * HDd;
    const float* bias = (p == 0 ? bq : (p == 1 ? bk : bv)) + h * HDd;
    __half* Cout      = (p == 0 ? g_Q : (p == 1 ? g_K : g_V));

    const int m0   = blockIdx.x * 128;
    const int t    = threadIdx.x;
    const int lane = t & 31;
    const int warp = t >> 5;
    const int g    = lane >> 2;
    const int tg   = lane & 3;
    const int wm   = warp >> 1;
    const int wn   = warp & 1;

    float acc[2][8][4];
#pragma unroll
    for (int mt = 0; mt < 2; mt++)
#pragma unroll
        for (int nt = 0; nt < 8; nt++)
#pragma unroll
            for (int i = 0; i < 4; i++) acc[mt][nt][i] = 0.f;

    auto load_stage = [&](int k0, int st) {
        __half* Ad = As + st * A_ST;
        __half* Bd = Bs + st * B_ST;
#pragma unroll
        for (int pp = 0; pp < 4; pp++) {
            int idx = t + pp * 256;
            int r = idx >> 3, c = (idx & 7) * 8;
            CP16(smaddr(Ad + r * 72 + c), g_x16 + (size_t)(m0 + r) * Dd + k0 + c);
        }
#pragma unroll
        for (int pp = 0; pp < 4; pp++) {
            int idx = t + pp * 256;
            int r = idx >> 4, c = (idx & 15) * 8;
            CP16(smaddr(Bd + r * 136 + c), W + (size_t)(k0 + r) * HDd + c);
        }
    };

    load_stage(0, 0);
    CP_COMMIT();

    for (int s = 0; s < 16; s++) {
        int cur = s & 1;
        if (s < 15) { load_stage((s + 1) * 64, cur ^ 1); CP_COMMIT(); CP_WAIT1(); }
        else        { CP_WAIT0(); }
        __syncthreads();

        const __half* Ac = As + cur * A_ST;
        const __half* Bc = Bs + cur * B_ST;
#pragma unroll
        for (int ks = 0; ks < 4; ks++) {
            int kk = ks * 16;
            uint32_t a[2][4];
#pragma unroll
            for (int mt = 0; mt < 2; mt++)
                ldsm4(a[mt][0], a[mt][1], a[mt][2], a[mt][3],
                      smaddr(Ac + (wm * 32 + mt * 16 + (lane & 15)) * 72 + kk + ((lane >> 4) << 3)));
            uint32_t bf[8][2];
#pragma unroll
            for (int nb = 0; nb < 4; nb++) {
                int n0 = wn * 64 + nb * 16;
                uint32_t r0, r1, r2, r3;
                ldsm4t(r0, r1, r2, r3,
                       smaddr(Bc + (kk + ((lane >> 3) & 1) * 8 + (lane & 7)) * 136 + n0 + (lane >> 4) * 8));
                bf[nb * 2][0] = r0; bf[nb * 2][1] = r1;
                bf[nb * 2 + 1][0] = r2; bf[nb * 2 + 1][1] = r3;
            }
#pragma unroll
            for (int mt = 0; mt < 2; mt++)
#pragma unroll
                for (int nt = 0; nt < 8; nt++)
                    mma16(acc[mt][nt], a[mt], bf[nt]);
        }
        __syncthreads();
    }

    // epilogue -> [B,H,N,HD] fp16 (+bias)
#pragma unroll
    for (int mt = 0; mt < 2; mt++) {
#pragma unroll
        for (int half = 0; half < 2; half++) {
            int r  = m0 + wm * 32 + mt * 16 + g + half * 8;
            int bb = r >> 10;
            int n  = r & 1023;
            __half* dst = Cout + (((size_t)(bb * Hh + h)) * Nn + n) * HDd;
#pragma unroll
            for (int nt = 0; nt < 8; nt++) {
                int cc = wn * 64 + nt * 8 + 2 * tg;
                *(half2*)(dst + cc) = __floats2half2_rn(
                    acc[mt][nt][half * 2 + 0] + bias[cc],
                    acc[mt][nt][half * 2 + 1] + bias[cc + 1]);
            }
        }
    }
}

// ============================================================
// Kernel 2: flash attention over COMPACTED valid tokens.
// Row-indirect cp.async loads via g_vidx; padded tail columns
// masked by col<nv (exact NEG path); out-of-range q rows clamp
// to row nv-1 and are never written. Masked q rows are handled
// by fill_invalid (uniform softmax = Vmean).
// grid (8 q-tiles, 8 heads, 16 batch), block 256, 2 CTAs/SM
// ============================================================
#define Q_SZ  17408            // 128*136 halves
#define KV_ST 8704             // 64*136 halves
#define ATTN_SMEM_BYTES ((Q_SZ + 4*KV_ST)*2)

__global__ __launch_bounds__(256, 2) void attn_kernel()
{
    extern __shared__ __half sm[];
    __half* Qs = sm;                    // [128][136]
    __half* Ks = sm + Q_SZ;             // [2][64][136]
    __half* Vs = Ks + 2 * KV_ST;        // [2][64][136]

    const int qt = blockIdx.x, h = blockIdx.y, b = blockIdx.z;
    const int nv = g_nv[b];
    const int q0 = qt * 128;
    if (q0 >= nv) return;

    const int t    = threadIdx.x;
    const int lane = t & 31;
    const int warp = t >> 5;
    const int g    = lane >> 2;
    const int tg   = lane & 3;
    const size_t bh = ((size_t)b * Hh + h) * Nn;
    const int* vb = g_vidx + b * Nn;
    const int rA = warp * 16 + g;
    const int rB = rA + 8;
    const int nkc = (nv + 63) >> 6;

    // Q tile (indirect rows, clamped to nv-1)
#pragma unroll
    for (int pp = 0; pp < 8; pp++) {
        int idx = t + pp * 256;
        int r = idx >> 4, c = (idx & 15) * 8;
        int j = q0 + r; j = (j < nv) ? j : (nv - 1);
        int tok = vb[j];
        CP16(smaddr(Qs + r * 136 + c), g_Q + (bh + tok) * HDd + c);
    }
    auto load_kv = [&](int kt, int st) {
        int k0 = kt * 64;
        __half* Kd = Ks + st * KV_ST;
        __half* Vd = Vs + st * KV_ST;
#pragma unroll
        for (int pp = 0; pp < 4; pp++) {
            int idx = t + pp * 256;
            int r = idx >> 4, c = (idx & 15) * 8;
            int j = k0 + r; j = (j < nv) ? j : (nv - 1);
            int tok = vb[j];
            CP16(smaddr(Kd + r * 136 + c), g_K + (bh + tok) * HDd + c);
            CP16(smaddr(Vd + r * 136 + c), g_V + (bh + tok) * HDd + c);
        }
    };
    load_kv(0, 0);
    CP_COMMIT();

    float mA = -INFINITY, mB = -INFINITY, lA = 0.f, lB = 0.f;

    float o[16][4];
#pragma unroll
    for (int jj = 0; jj < 16; jj++)
#pragma unroll
        for (int i = 0; i < 4; i++) o[jj][i] = 0.f;

    for (int kt = 0; kt < nkc; kt++) {
        const int cur = kt & 1;
        if (kt < nkc - 1) { load_kv(kt + 1, cur ^ 1); CP_COMMIT(); CP_WAIT1(); }
        else              { CP_WAIT0(); }
        __syncthreads();

        const __half* Kst = Ks + cur * KV_ST;
        const __half* Vst = Vs + cur * KV_ST;

        float s[8][4];
#pragma unroll
        for (int nt = 0; nt < 8; nt++)
#pragma unroll
            for (int i = 0; i < 4; i++) s[nt][i] = 0.f;

#pragma unroll
        for (int ks = 0; ks < 8; ks++) {
            int kk = ks * 16;
            uint32_t a[4];
            ldsm4(a[0], a[1], a[2], a[3],
                  smaddr(Qs + (warp * 16 + (lane & 15)) * 136 + kk + ((lane >> 4) << 3)));
#pragma unroll
            for (int nb = 0; nb < 4; nb++) {
                int n0 = nb * 16;
                uint32_t r0, r1, r2, r3;
                ldsm4(r0, r1, r2, r3,
                      smaddr(Kst + (n0 + ((lane >> 4) << 3) + (lane & 7)) * 136 + kk + ((lane >> 3) & 1) * 8));
                uint32_t b0[2] = { r0, r1 }, b1[2] = { r2, r3 };
                mma16(s[nb * 2], a, b0);
                mma16(s[nb * 2 + 1], a, b1);
            }
        }

        // ---- scale + mask padded tail columns (col >= nv) ----
        const int cb = kt * 64;
#pragma unroll
        for (int nt = 0; nt < 8; nt++) {
            int c0 = cb + nt * 8 + 2 * tg;
            bool v0 = (c0     < nv);
            bool v1 = (c0 + 1 < nv);
            s[nt][0] = v0 ? s[nt][0] * SCALE2 : NEG_F;
            s[nt][1] = v1 ? s[nt][1] * SCALE2 : NEG_F;
            s[nt][2] = v0 ? s[nt][2] * SCALE2 : NEG_F;
            s[nt][3] = v1 ? s[nt][3] * SCALE2 : NEG_F;
        }

        float tmA = s[0][0], tmB = s[0][2];
#pragma unroll
        for (int nt = 0; nt < 8; nt++) {
            tmA = fmaxf(tmA, fmaxf(s[nt][0], s[nt][1]));
            tmB = fmaxf(tmB, fmaxf(s[nt][2], s[nt][3]));
        }
        tmA = fmaxf(tmA, __shfl_xor_sync(0xffffffffu, tmA, 1));
        tmA = fmaxf(tmA, __shfl_xor_sync(0xffffffffu, tmA, 2));
        tmB = fmaxf(tmB, __shfl_xor_sync(0xffffffffu, tmB, 1));
        tmB = fmaxf(tmB, __shfl_xor_sync(0xffffffffu, tmB, 2));

        const bool updA = tmA > mA;
        const bool updB = tmB > mB;
        float mnA = updA ? tmA : mA;
        float mnB = updB ? tmB : mB;
        float alA = updA ? ex2f(mA - mnA) : 1.f;
        float alB = updB ? ex2f(mB - mnB) : 1.f;
        mA = mnA; mB = mnB;

        uint32_t pA[8], pB[8];
        float sumA = 0.f, sumB = 0.f;
#pragma unroll
        for (int nt = 0; nt < 8; nt++) {
            uint32_t hA = packh2(s[nt][0] - mnA, s[nt][1] - mnA);
            uint32_t hB = packh2(s[nt][2] - mnB, s[nt][3] - mnB);
            uint32_t eA = ex2h2(hA);
            uint32_t eB = ex2h2(hB);
            pA[nt] = eA;
            pB[nt] = eB;
            float2 fA = __half22float2(*(half2*)&eA);
            float2 fB = __half22float2(*(half2*)&eB);
            sumA += fA.x + fA.y;
            sumB += fB.x + fB.y;
        }
        sumA += __shfl_xor_sync(0xffffffffu, sumA, 1);
        sumA += __shfl_xor_sync(0xffffffffu, sumA, 2);
        sumB += __shfl_xor_sync(0xffffffffu, sumB, 1);
        sumB += __shfl_xor_sync(0xffffffffu, sumB, 2);
        lA = lA * alA + sumA;
        lB = lB * alB + sumB;

        if (__any_sync(0xffffffffu, updA | updB)) {
#pragma unroll
            for (int jj = 0; jj < 16; jj++) {
                o[jj][0] *= alA; o[jj][1] *= alA;
                o[jj][2] *= alB; o[jj][3] *= alB;
            }
        }

#pragma unroll
        for (int i = 0; i < 4; i++) {
            uint32_t a[4] = { pA[2 * i], pB[2 * i], pA[2 * i + 1], pB[2 * i + 1] };
#pragma unroll
            for (int nb = 0; nb < 8; nb++) {
                int n0 = nb * 16;
                uint32_t r0, r1, r2, r3;
                ldsm4t(r0, r1, r2, r3,
                       smaddr(Vst + (i * 16 + ((lane >> 3) & 1) * 8 + (lane & 7)) * 136 + n0 + (lane >> 4) * 8));
                uint32_t b0[2] = { r0, r1 }, b1[2] = { r2, r3 };
                mma16(o[nb * 2], a, b0);
                mma16(o[nb * 2 + 1], a, b1);
            }
        }
        __syncthreads();
    }

    // scatter epilogue: only rows < nv, to token vidx[j]
    const float invA = 1.f / lA;
    const float invB = 1.f / lB;
    const int jA = q0 + rA, jB = q0 + rB;
    if (jA < nv) {
        __half* dA = g_O16 + ((size_t)(b * Nn) + vb[jA]) * Dd + h * HDd;
#pragma unroll
        for (int jj = 0; jj < 16; jj++) {
            int c0 = jj * 8 + 2 * tg;
            *(half2*)(dA + c0) = __floats2half2_rn(o[jj][0] * invA, o[jj][1] * invA);
        }
    }
    if (jB < nv) {
        __half* dB = g_O16 + ((size_t)(b * Nn) + vb[jB]) * Dd + h * HDd;
#pragma unroll
        for (int jj = 0; jj < 16; jj++) {
            int c0 = jj * 8 + 2 * tg;
            *(half2*)(dB + c0) = __floats2half2_rn(o[jj][2] * invB, o[jj][3] * invB);
        }
    }
}

// ============================================================
// Kernel 3: out = O16 @ Wfc16 + bfc (fp32 out)
// grid (128 m-tiles, 8 n-tiles), block 256
// ============================================================
__global__ __launch_bounds__(256) void fc_gemm(
    const float* __restrict__ bfc, float* __restrict__ out)
{
    extern __shared__ __half sm[];
    __half* As = sm;
    __half* Bs = sm + 2*A_ST;

    const int m0 = blockIdx.x * 128;
    const int n0 = blockIdx.y * 128;
    const int t    = threadIdx.x;
    const int lane = t & 31;
    const int warp = t >> 5;
    const int g    = lane >> 2;
    const int tg   = lane & 3;
    const int wm   = warp >> 1;
    const int wn   = warp & 1;

    float acc[2][8][4];
#pragma unroll
    for (int mt = 0; mt < 2; mt++)
#pragma unroll
        for (int nt = 0; nt < 8; nt++)
#pragma unroll
            for (int i = 0; i < 4; i++) acc[mt][nt][i] = 0.f;

    auto load_stage = [&](int k0, int st) {
        __half* Ad = As + st * A_ST;
        __half* Bd = Bs + st * B_ST;
#pragma unroll
        for (int pp = 0; pp < 4; pp++) {
            int idx = t + pp * 256;
            int r = idx >> 3, c = (idx & 7) * 8;
            CP16(smaddr(Ad + r * 72 + c), g_O16 + (size_t)(m0 + r) * Dd + k0 + c);
        }
#pragma unroll
        for (int pp = 0; pp < 4; pp++) {
            int idx = t + pp * 256;
            int r = idx >> 4, c = (idx & 15) * 8;
            CP16(smaddr(Bd + r * 136 + c), g_Wfc16 + (size_t)(k0 + r) * Dd + n0 + c);
        }
    };

    load_stage(0, 0);
    CP_COMMIT();

    for (int s = 0; s < 16; s++) {
        int cur = s & 1;
        if (s < 15) { load_stage((s + 1) * 64, cur ^ 1); CP_COMMIT(); CP_WAIT1(); }
        else        { CP_WAIT0(); }
        __syncthreads();

        const __half* Ac = As + cur * A_ST;
        const __half* Bc = Bs + cur * B_ST;
#pragma unroll
        for (int ks = 0; ks < 4; ks++) {
            int kk = ks * 16;
            uint32_t a[2][4];
#pragma unroll
            for (int mt = 0; mt < 2; mt++)
                ldsm4(a[mt][0], a[mt][1], a[mt][2], a[mt][3],
                      smaddr(Ac + (wm * 32 + mt * 16 + (lane & 15)) * 72 + kk + ((lane >> 4) << 3)));
            uint32_t bf[8][2];
#pragma unroll
            for (int nb = 0; nb < 4; nb++) {
                int nn0 = wn * 64 + nb * 16;
                uint32_t r0, r1, r2, r3;
                ldsm4t(r0, r1, r2, r3,
                       smaddr(Bc + (kk + ((lane >> 3) & 1) * 8 + (lane & 7)) * 136 + nn0 + (lane >> 4) * 8));
                bf[nb * 2][0] = r0; bf[nb * 2][1] = r1;
                bf[nb * 2 + 1][0] = r2; bf[nb * 2 + 1][1] = r3;
            }
#pragma unroll
            for (int mt = 0; mt < 2; mt++)
#pragma unroll
                for (int nt = 0; nt < 8; nt++)
                    mma16(acc[mt][nt], a[mt], bf[nt]);
        }
        __syncthreads();
    }

#pragma unroll
    for (int mt = 0; mt < 2; mt++) {
#pragma unroll
        for (int half = 0; half < 2; half++) {
            int r = m0 + wm * 32 + mt * 16 + g + half * 8;
            float* dst = out + (size_t)r * Dd + n0;
#pragma unroll
            for (int nt = 0; nt < 8; nt++) {
                int cc = wn * 64 + nt * 8 + 2 * tg;
                float2 v;
                v.x = acc[mt][nt][half * 2 + 0] + bfc[n0 + cc];
                v.y = acc[mt][nt][half * 2 + 1] + bfc[n0 + cc + 1];
                *(float2*)(dst + cc) = v;
            }
        }
    }
}

// ============================================================
extern "C" void kernel_launch(void* const* d_in, const int* in_sizes, int n_in,
                              void* d_out, int out_size)
{
    const float* x      = (const float*)d_in[0];
    const int*   x_mask = (const int*)  d_in[1];
    const float* Wq     = (const float*)d_in[2];
    const float* bq     = (const float*)d_in[3];
    const float* Wk     = (const float*)d_in[4];
    const float* bk     = (const float*)d_in[5];
    const float* Wv     = (const float*)d_in[6];
    const float* bv     = (const float*)d_in[7];
    const float* Wfc    = (const float*)d_in[8];
    const float* bfc    = (const float*)d_in[9];
    float* out = (float*)d_out;

    static bool attr_done = false;
    if (!attr_done) {
        cudaFuncSetAttribute(attn_kernel, cudaFuncAttributeMaxDynamicSharedMemorySize, ATTN_SMEM_BYTES);
        cudaFuncSetAttribute(qkv_gemm,    cudaFuncAttributeMaxDynamicSharedMemorySize, GEMM_SMEM);
        cudaFuncSetAttribute(fc_gemm,     cudaFuncAttributeMaxDynamicSharedMemorySize, GEMM_SMEM);
        attr_done = true;
    }

    convert_all<<<2048, 256>>>(x, Wq, Wk, Wv, Wfc);
    build_valid<<<16, 1024>>>(x_mask);
    qkv_gemm<<<dim3(128, 1, 24), 256, GEMM_SMEM>>>(bq, bk, bv);
    vsum_kernel<<<dim3(8, 16), 128>>>();
    fill_invalid<<<dim3(512, 16), 256>>>(x_mask);
    attn_kernel<<<dim3(8, 8, 16), 256, ATTN_SMEM_BYTES>>>();
    fc_gemm<<<dim3(128, 8, 1), 256, GEMM_SMEM>>>(bfc, out);
}

// round 16
// speedup vs baseline: 1.5744x; 1.1917x over previous
#include <cuda_runtime.h>
#include <cuda_fp16.h>
#include <cstdint>
#include <math.h>

#define Bb 16
#define Nn 1024
#define Dd 1024
#define Hh 8
#define HDd 128
#define SCALE2  (0.08838834764831845f * 1.4426950408889634f)
#define NEG_F  -1e30f

// ---------------- scratch (static; no allocation allowed) ----------------
__device__ __align__(16) __half g_x16 [Bb*Nn*Dd];
__device__ __align__(16) __half g_Wq16[Hh*Dd*HDd];
__device__ __align__(16) __half g_Wk16[Hh*Dd*HDd];
__device__ __align__(16) __half g_Wv16[Hh*Dd*HDd];
__device__ __align__(16) __half g_Wfc16[Dd*Dd];
__device__ __align__(16) __half g_Q[Bb*Hh*Nn*HDd];    // [B,H,N,HD]
__device__ __align__(16) __half g_K[Bb*Hh*Nn*HDd];
__device__ __align__(16) __half g_V[Bb*Hh*Nn*HDd];
__device__ __align__(16) __half g_O16[Bb*Nn*Dd];      // [B,N,D]
__device__ int   g_vidx[Bb*Nn];                       // per-batch compacted tokens
__device__ int   g_nv[Bb];
__device__ int   g_off[Bb];                           // exclusive scan of g_nv
__device__ int   g_nvt;                               // total valid
__device__ int   g_gidx[Bb*Nn];                       // global compacted rows (b*N+tok)
__device__ float g_Vmean[Bb*Hh*HDd];

// ---------------- helpers ----------------
__device__ __forceinline__ uint32_t smaddr(const void* p) {
    return (uint32_t)__cvta_generic_to_shared(p);
}
__device__ __forceinline__ void ldsm4(uint32_t& r0, uint32_t& r1, uint32_t& r2, uint32_t& r3, uint32_t a) {
    asm volatile("ldmatrix.sync.aligned.m8n8.x4.shared.b16 {%0,%1,%2,%3}, [%4];"
                 : "=r"(r0), "=r"(r1), "=r"(r2), "=r"(r3) : "r"(a));
}
__device__ __forceinline__ void ldsm4t(uint32_t& r0, uint32_t& r1, uint32_t& r2, uint32_t& r3, uint32_t a) {
    asm volatile("ldmatrix.sync.aligned.m8n8.x4.trans.shared.b16 {%0,%1,%2,%3}, [%4];"
                 : "=r"(r0), "=r"(r1), "=r"(r2), "=r"(r3) : "r"(a));
}
__device__ __forceinline__ void mma16(float c[4], const uint32_t a[4], const uint32_t b[2]) {
    asm volatile(
        "mma.sync.aligned.m16n8k16.row.col.f32.f16.f16.f32 "
        "{%0,%1,%2,%3}, {%4,%5,%6,%7}, {%8,%9}, {%0,%1,%2,%3};"
        : "+f"(c[0]), "+f"(c[1]), "+f"(c[2]), "+f"(c[3])
        : "r"(a[0]), "r"(a[1]), "r"(a[2]), "r"(a[3]), "r"(b[0]), "r"(b[1]));
}
__device__ __forceinline__ uint32_t packh2(float a, float b) {
    __half2 h = __floats2half2_rn(a, b);
    return *(uint32_t*)&h;
}
__device__ __forceinline__ uint32_t ex2h2(uint32_t x) {
    uint32_t r;
    asm("ex2.approx.f16x2 %0, %1;" : "=r"(r) : "r"(x));
    return r;
}
__device__ __forceinline__ float ex2f(float x) {
    float r;
    asm("ex2.approx.f32 %0, %1;" : "=f"(r) : "f"(x));
    return r;
}

#define CP16(dst_sm, src_g) \
    asm volatile("cp.async.cg.shared.global [%0], [%1], 16;" :: "r"(dst_sm), "l"(src_g))
#define CP_COMMIT() asm volatile("cp.async.commit_group;")
#define CP_WAIT0()  asm volatile("cp.async.wait_group 0;")
#define CP_WAIT1()  asm volatile("cp.async.wait_group 1;")

// ============================================================
// Kernel 0: convert fp32 inputs to fp16 scratch
// ============================================================
#define CV_X  4194304
#define CV_W  262144
__global__ __launch_bounds__(256) void convert_all(
    const float* __restrict__ x,  const float* __restrict__ Wq,
    const float* __restrict__ Wk, const float* __restrict__ Wv,
    const float* __restrict__ Wfc)
{
    const int total = CV_X + 4*CV_W;
    for (int i = blockIdx.x * blockDim.x + threadIdx.x; i < total; i += gridDim.x * blockDim.x) {
        const float* src; __half* dst; int off;
        if (i < CV_X)                 { src = x;   dst = g_x16;  off = i; }
        else if (i < CV_X + CV_W)     { src = Wq;  dst = g_Wq16; off = i - CV_X; }
        else if (i < CV_X + 2*CV_W)   { src = Wk;  dst = g_Wk16; off = i - CV_X - CV_W; }
        else if (i < CV_X + 3*CV_W)   { src = Wv;  dst = g_Wv16; off = i - CV_X - 2*CV_W; }
        else                          { src = Wfc; dst = g_Wfc16; off = i - CV_X - 3*CV_W; }
        float4 v = ((const float4*)src)[off];
        uint2 u;
        u.x = packh2(v.x, v.y);
        u.y = packh2(v.z, v.w);
        ((uint2*)dst)[off] = u;
    }
}

// ============================================================
// Kernel 0b: per-batch compaction (also zeroes nothing else needed)
// grid (16), block 1024
// ============================================================
__global__ __launch_bounds__(1024) void build_valid(const int* __restrict__ x_mask)
{
    __shared__ int pre[1024];
    const int b = blockIdx.x, t = threadIdx.x;
    const int m = x_mask[b * Nn + t];
    pre[t] = m;
    __syncthreads();
    for (int off = 1; off < 1024; off <<= 1) {
        int v = (t >= off) ? pre[t - off] : 0;
        __syncthreads();
        pre[t] += v;
        __syncthreads();
    }
    if (m) g_vidx[b * Nn + pre[t] - 1] = t;
    if (t == 1023) g_nv[b] = pre[1023];
}

// Kernel 0b2: scan batch counts (trivial)
__global__ void scan16()
{
    if (threadIdx.x == 0) {
        int s = 0;
        for (int b = 0; b < Bb; b++) { g_off[b] = s; s += g_nv[b]; }
        g_nvt = s;
    }
}

// Kernel 0b3: build global compacted row list
__global__ __launch_bounds__(1024) void gather_valid()
{
    const int b = blockIdx.x, t = threadIdx.x;
    if (t < g_nv[b]) g_gidx[g_off[b] + t] = b * Nn + g_vidx[b * Nn + t];
}

// ============================================================
// Kernel 0c: Vmean, block (128,4), grid (8 h, 16 b)
// ============================================================
__global__ __launch_bounds__(512) void vsum_kernel()
{
    __shared__ float part[4][128];
    const int h = blockIdx.x, b = blockIdx.y;
    const int e = threadIdx.x, q = threadIdx.y;
    const __half* V = g_V + ((size_t)(b * Hh + h) * Nn + q * 256) * HDd + e;
    float s0 = 0.f, s1 = 0.f, s2 = 0.f, s3 = 0.f;
    for (int n = 0; n < 256; n += 4) {
        s0 += __half2float(V[(size_t)(n + 0) * HDd]);
        s1 += __half2float(V[(size_t)(n + 1) * HDd]);
        s2 += __half2float(V[(size_t)(n + 2) * HDd]);
        s3 += __half2float(V[(size_t)(n + 3) * HDd]);
    }
    part[q][e] = (s0 + s1) + (s2 + s3);
    __syncthreads();
    if (q == 0)
        g_Vmean[(b * Hh + h) * HDd + e] =
            (part[0][e] + part[1][e] + part[2][e] + part[3][e]) * (1.f / 1024.f);
}

// ============================================================
// Kernel 0d: masked q rows -> o = Vmean
// ============================================================
__global__ __launch_bounds__(256) void fill_invalid(const int* __restrict__ x_mask)
{
    const int b = blockIdx.y;
    const int w = blockIdx.x * 256 + threadIdx.x;
    const int tok = w >> 7;
    const int rem = w & 127;
    const int h   = rem >> 4;
    const int cc  = (rem & 15) * 8;
    if (x_mask[b * Nn + tok]) return;
    const float* vm = g_Vmean + (b * Hh + h) * HDd + cc;
    __half* dst = g_O16 + ((size_t)(b * Nn) + tok) * Dd + h * HDd + cc;
    uint4 u;
    u.x = packh2(vm[0], vm[1]);
    u.y = packh2(vm[2], vm[3]);
    u.z = packh2(vm[4], vm[5]);
    u.w = packh2(vm[6], vm[7]);
    *(uint4*)dst = u;
}

// ============================================================
// GEMM smem geometry: 2-stage, k-depth 64, CTA 128x128, warp 32x64
// ============================================================
#define A_ST 9216     // 128 * 72 halves
#define B_ST 8704     // 64 * 136 halves
#define GEMM_SMEM ((2*(A_ST + B_ST)) * 2)

// ============================================================
// Kernel 1a: V projection (full rows).  grid (128, 1, 8)
// ============================================================
__global__ __launch_bounds__(256) void v_gemm(const float* __restrict__ bv)
{
    extern __shared__ __half sm[];
    __half* As = sm;
    __half* Bs = sm + 2*A_ST;

    const int h = blockIdx.z;
    const __half* W = g_Wv16 + (size_t)h * Dd * HDd;
    const float* bias = bv + h * HDd;

    const int m0   = blockIdx.x * 128;
    const int t    = threadIdx.x;
    const int lane = t & 31;
    const int warp = t >> 5;
    const int g    = lane >> 2;
    const int tg   = lane & 3;
    const int wm   = warp >> 1;
    const int wn   = warp & 1;

    float acc[2][8][4];
#pragma unroll
    for (int mt = 0; mt < 2; mt++)
#pragma unroll
        for (int nt = 0; nt < 8; nt++)
#pragma unroll
            for (int i = 0; i < 4; i++) acc[mt][nt][i] = 0.f;

    auto load_stage = [&](int k0, int st) {
        __half* Ad = As + st * A_ST;
        __half* Bd = Bs + st * B_ST;
#pragma unroll
        for (int pp = 0; pp < 4; pp++) {
            int idx = t + pp * 256;
            int r = idx >> 3, c = (idx & 7) * 8;
            CP16(smaddr(Ad + r * 72 + c), g_x16 + (size_t)(m0 + r) * Dd + k0 + c);
        }
#pragma unroll
        for (int pp = 0; pp < 4; pp++) {
            int idx = t + pp * 256;
            int r = idx >> 4, c = (idx & 15) * 8;
            CP16(smaddr(Bd + r * 136 + c), W + (size_t)(k0 + r) * HDd + c);
        }
    };

    load_stage(0, 0);
    CP_COMMIT();

    for (int s = 0; s < 16; s++) {
        int cur = s & 1;
        if (s < 15) { load_stage((s + 1) * 64, cur ^ 1); CP_COMMIT(); CP_WAIT1(); }
        else        { CP_WAIT0(); }
        __syncthreads();

        const __half* Ac = As + cur * A_ST;
        const __half* Bc = Bs + cur * B_ST;
#pragma unroll
        for (int ks = 0; ks < 4; ks++) {
            int kk = ks * 16;
            uint32_t a[2][4];
#pragma unroll
            for (int mt = 0; mt < 2; mt++)
                ldsm4(a[mt][0], a[mt][1], a[mt][2], a[mt][3],
                      smaddr(Ac + (wm * 32 + mt * 16 + (lane & 15)) * 72 + kk + ((lane >> 4) << 3)));
            uint32_t bf[8][2];
#pragma unroll
            for (int nb = 0; nb < 4; nb++) {
                int n0 = wn * 64 + nb * 16;
                uint32_t r0, r1, r2, r3;
                ldsm4t(r0, r1, r2, r3,
                       smaddr(Bc + (kk + ((lane >> 3) & 1) * 8 + (lane & 7)) * 136 + n0 + (lane >> 4) * 8));
                bf[nb * 2][0] = r0; bf[nb * 2][1] = r1;
                bf[nb * 2 + 1][0] = r2; bf[nb * 2 + 1][1] = r3;
            }
#pragma unroll
            for (int mt = 0; mt < 2; mt++)
#pragma unroll
                for (int nt = 0; nt < 8; nt++)
                    mma16(acc[mt][nt], a[mt], bf[nt]);
        }
        __syncthreads();
    }

#pragma unroll
    for (int mt = 0; mt < 2; mt++) {
#pragma unroll
        for (int half = 0; half < 2; half++) {
            int r  = m0 + wm * 32 + mt * 16 + g + half * 8;
            int bb = r >> 10;
            int n  = r & 1023;
            __half* dst = g_V + (((size_t)(bb * Hh + h)) * Nn + n) * HDd;
#pragma unroll
            for (int nt = 0; nt < 8; nt++) {
                int cc = wn * 64 + nt * 8 + 2 * tg;
                *(half2*)(dst + cc) = __floats2half2_rn(
                    acc[mt][nt][half * 2 + 0] + bias[cc],
                    acc[mt][nt][half * 2 + 1] + bias[cc + 1]);
            }
        }
    }
}

// ============================================================
// Kernel 1b: Q/K projection over COMPACTED global rows.
// grid (128 m-tiles, 1, 16): p = z>>3 (0=Q,1=K), h = z&7.
// Early-exit when m0 >= nvt; row indices cached in smem.
// ============================================================
__global__ __launch_bounds__(256) void qk_gemm(
    const float* __restrict__ bq, const float* __restrict__ bk)
{
    __shared__ int rows[128];
    extern __shared__ __half sm[];
    __half* As = sm;
    __half* Bs = sm + 2*A_ST;

    const int z = blockIdx.z;
    const int p = z >> 3;
    const int h = z & 7;
    const int nvt = g_nvt;
    const int m0 = blockIdx.x * 128;
    if (m0 >= nvt) return;

    const __half* W   = (p == 0 ? g_Wq16 : g_Wk16) + (size_t)h * Dd * HDd;
    const float* bias = (p == 0 ? bq : bk) + h * HDd;
    __half* Cout      = (p == 0 ? g_Q : g_K);

    const int t    = threadIdx.x;
    const int lane = t & 31;
    const int warp = t >> 5;
    const int g    = lane >> 2;
    const int tg   = lane & 3;
    const int wm   = warp >> 1;
    const int wn   = warp & 1;

    if (t < 128) {
        int j = m0 + t;
        j = (j < nvt) ? j : (nvt - 1);
        rows[t] = g_gidx[j];
    }
    __syncthreads();

    float acc[2][8][4];
#pragma unroll
    for (int mt = 0; mt < 2; mt++)
#pragma unroll
        for (int nt = 0; nt < 8; nt++)
#pragma unroll
            for (int i = 0; i < 4; i++) acc[mt][nt][i] = 0.f;

    auto load_stage = [&](int k0, int st) {
        __half* Ad = As + st * A_ST;
        __half* Bd = Bs + st * B_ST;
#pragma unroll
        for (int pp = 0; pp < 4; pp++) {
            int idx = t + pp * 256;
            int r = idx >> 3, c = (idx & 7) * 8;
            CP16(smaddr(Ad + r * 72 + c), g_x16 + (size_t)rows[r] * Dd + k0 + c);
        }
#pragma unroll
        for (int pp = 0; pp < 4; pp++) {
            int idx = t + pp * 256;
            int r = idx >> 4, c = (idx & 15) * 8;
            CP16(smaddr(Bd + r * 136 + c), W + (size_t)(k0 + r) * HDd + c);
        }
    };

    load_stage(0, 0);
    CP_COMMIT();

    for (int s = 0; s < 16; s++) {
        int cur = s & 1;
        if (s < 15) { load_stage((s + 1) * 64, cur ^ 1); CP_COMMIT(); CP_WAIT1(); }
        else        { CP_WAIT0(); }
        __syncthreads();

        const __half* Ac = As + cur * A_ST;
        const __half* Bc = Bs + cur * B_ST;
#pragma unroll
        for (int ks = 0; ks < 4; ks++) {
            int kk = ks * 16;
            uint32_t a[2][4];
#pragma unroll
            for (int mt = 0; mt < 2; mt++)
                ldsm4(a[mt][0], a[mt][1], a[mt][2], a[mt][3],
                      smaddr(Ac + (wm * 32 + mt * 16 + (lane & 15)) * 72 + kk + ((lane >> 4) << 3)));
            uint32_t bf[8][2];
#pragma unroll
            for (int nb = 0; nb < 4; nb++) {
                int n0 = wn * 64 + nb * 16;
                uint32_t r0, r1, r2, r3;
                ldsm4t(r0, r1, r2, r3,
                       smaddr(Bc + (kk + ((lane >> 3) & 1) * 8 + (lane & 7)) * 136 + n0 + (lane >> 4) * 8));
                bf[nb * 2][0] = r0; bf[nb * 2][1] = r1;
                bf[nb * 2 + 1][0] = r2; bf[nb * 2 + 1][1] = r3;
            }
#pragma unroll
            for (int mt = 0; mt < 2; mt++)
#pragma unroll
                for (int nt = 0; nt < 8; nt++)
                    mma16(acc[mt][nt], a[mt], bf[nt]);
        }
        __syncthreads();
    }

    // scatter epilogue via rows[]
#pragma unroll
    for (int mt = 0; mt < 2; mt++) {
#pragma unroll
        for (int half = 0; half < 2; half++) {
            int jl = wm * 32 + mt * 16 + g + half * 8;
            int gid = rows[jl];
            int bb = gid >> 10;
            int n  = gid & 1023;
            __half* dst = Cout + (((size_t)(bb * Hh + h)) * Nn + n) * HDd;
#pragma unroll
            for (int nt = 0; nt < 8; nt++) {
                int cc = wn * 64 + nt * 8 + 2 * tg;
                *(half2*)(dst + cc) = __floats2half2_rn(
                    acc[mt][nt][half * 2 + 0] + bias[cc],
                    acc[mt][nt][half * 2 + 1] + bias[cc + 1]);
            }
        }
    }
}

// ============================================================
// Kernel 2: flash attention over compacted valid tokens (r15, unchanged)
// ============================================================
#define Q_SZ  17408
#define KV_ST 8704
#define ATTN_SMEM_BYTES ((Q_SZ + 4*KV_ST)*2)

__global__ __launch_bounds__(256, 2) void attn_kernel()
{
    extern __shared__ __half sm[];
    __half* Qs = sm;
    __half* Ks = sm + Q_SZ;
    __half* Vs = Ks + 2 * KV_ST;

    const int qt = blockIdx.x, h = blockIdx.y, b = blockIdx.z;
    const int nv = g_nv[b];
    const int q0 = qt * 128;
    if (q0 >= nv) return;

    const int t    = threadIdx.x;
    const int lane = t & 31;
    const int warp = t >> 5;
    const int g    = lane >> 2;
    const int tg   = lane & 3;
    const size_t bh = ((size_t)b * Hh + h) * Nn;
    const int* vb = g_vidx + b * Nn;
    const int rA = warp * 16 + g;
    const int rB = rA + 8;
    const int nkc = (nv + 63) >> 6;

#pragma unroll
    for (int pp = 0; pp < 8; pp++) {
        int idx = t + pp * 256;
        int r = idx >> 4, c = (idx & 15) * 8;
        int j = q0 + r; j = (j < nv) ? j : (nv - 1);
        int tok = vb[j];
        CP16(smaddr(Qs + r * 136 + c), g_Q + (bh + tok) * HDd + c);
    }
    auto load_kv = [&](int kt, int st) {
        int k0 = kt * 64;
        __half* Kd = Ks + st * KV_ST;
        __half* Vd = Vs + st * KV_ST;
#pragma unroll
        for (int pp = 0; pp < 4; pp++) {
            int idx = t + pp * 256;
            int r = idx >> 4, c = (idx & 15) * 8;
            int j = k0 + r; j = (j < nv) ? j : (nv - 1);
            int tok = vb[j];
            CP16(smaddr(Kd + r * 136 + c), g_K + (bh + tok) * HDd + c);
            CP16(smaddr(Vd + r * 136 + c), g_V + (bh + tok) * HDd + c);
        }
    };
    load_kv(0, 0);
    CP_COMMIT();

    float mA = -INFINITY, mB = -INFINITY, lA = 0.f, lB = 0.f;

    float o[16][4];
#pragma unroll
    for (int jj = 0; jj < 16; jj++)
#pragma unroll
        for (int i = 0; i < 4; i++) o[jj][i] = 0.f;

    for (int kt = 0; kt < nkc; kt++) {
        const int cur = kt & 1;
        if (kt < nkc - 1) { load_kv(kt + 1, cur ^ 1); CP_COMMIT(); CP_WAIT1(); }
        else              { CP_WAIT0(); }
        __syncthreads();

        const __half* Kst = Ks + cur * KV_ST;
        const __half* Vst = Vs + cur * KV_ST;

        float s[8][4];
#pragma unroll
        for (int nt = 0; nt < 8; nt++)
#pragma unroll
            for (int i = 0; i < 4; i++) s[nt][i] = 0.f;

#pragma unroll
        for (int ks = 0; ks < 8; ks++) {
            int kk = ks * 16;
            uint32_t a[4];
            ldsm4(a[0], a[1], a[2], a[3],
                  smaddr(Qs + (warp * 16 + (lane & 15)) * 136 + kk + ((lane >> 4) << 3)));
#pragma unroll
            for (int nb = 0; nb < 4; nb++) {
                int n0 = nb * 16;
                uint32_t r0, r1, r2, r3;
                ldsm4(r0, r1, r2, r3,
                      smaddr(Kst + (n0 + ((lane >> 4) << 3) + (lane & 7)) * 136 + kk + ((lane >> 3) & 1) * 8));
                uint32_t b0[2] = { r0, r1 }, b1[2] = { r2, r3 };
                mma16(s[nb * 2], a, b0);
                mma16(s[nb * 2 + 1], a, b1);
            }
        }

        const int cb = kt * 64;
#pragma unroll
        for (int nt = 0; nt < 8; nt++) {
            int c0 = cb + nt * 8 + 2 * tg;
            bool v0 = (c0     < nv);
            bool v1 = (c0 + 1 < nv);
            s[nt][0] = v0 ? s[nt][0] * SCALE2 : NEG_F;
            s[nt][1] = v1 ? s[nt][1] * SCALE2 : NEG_F;
            s[nt][2] = v0 ? s[nt][2] * SCALE2 : NEG_F;
            s[nt][3] = v1 ? s[nt][3] * SCALE2 : NEG_F;
        }

        float tmA = s[0][0], tmB = s[0][2];
#pragma unroll
        for (int nt = 0; nt < 8; nt++) {
            tmA = fmaxf(tmA, fmaxf(s[nt][0], s[nt][1]));
            tmB = fmaxf(tmB, fmaxf(s[nt][2], s[nt][3]));
        }
        tmA = fmaxf(tmA, __shfl_xor_sync(0xffffffffu, tmA, 1));
        tmA = fmaxf(tmA, __shfl_xor_sync(0xffffffffu, tmA, 2));
        tmB = fmaxf(tmB, __shfl_xor_sync(0xffffffffu, tmB, 1));
        tmB = fmaxf(tmB, __shfl_xor_sync(0xffffffffu, tmB, 2));

        const bool updA = tmA > mA;
        const bool updB = tmB > mB;
        float mnA = updA ? tmA : mA;
        float mnB = updB ? tmB : mB;
        float alA = updA ? ex2f(mA - mnA) : 1.f;
        float alB = updB ? ex2f(mB - mnB) : 1.f;
        mA = mnA; mB = mnB;

        uint32_t pA[8], pB[8];
        float sumA = 0.f, sumB = 0.f;
#pragma unroll
        for (int nt = 0; nt < 8; nt++) {
            uint32_t hA = packh2(s[nt][0] - mnA, s[nt][1] - mnA);
            uint32_t hB = packh2(s[nt][2] - mnB, s[nt][3] - mnB);
            uint32_t eA = ex2h2(hA);
            uint32_t eB = ex2h2(hB);
            pA[nt] = eA;
            pB[nt] = eB;
            float2 fA = __half22float2(*(half2*)&eA);
            float2 fB = __half22float2(*(half2*)&eB);
            sumA += fA.x + fA.y;
            sumB += fB.x + fB.y;
        }
        sumA += __shfl_xor_sync(0xffffffffu, sumA, 1);
        sumA += __shfl_xor_sync(0xffffffffu, sumA, 2);
        sumB += __shfl_xor_sync(0xffffffffu, sumB, 1);
        sumB += __shfl_xor_sync(0xffffffffu, sumB, 2);
        lA = lA * alA + sumA;
        lB = lB * alB + sumB;

        if (__any_sync(0xffffffffu, updA | updB)) {
#pragma unroll
            for (int jj = 0; jj < 16; jj++) {
                o[jj][0] *= alA; o[jj][1] *= alA;
                o[jj][2] *= alB; o[jj][3] *= alB;
            }
        }

#pragma unroll
        for (int i = 0; i < 4; i++) {
            uint32_t a[4] = { pA[2 * i], pB[2 * i], pA[2 * i + 1], pB[2 * i + 1] };
#pragma unroll
            for (int nb = 0; nb < 8; nb++) {
                int n0 = nb * 16;
                uint32_t r0, r1, r2, r3;
                ldsm4t(r0, r1, r2, r3,
                       smaddr(Vst + (i * 16 + ((lane >> 3) & 1) * 8 + (lane & 7)) * 136 + n0 + (lane >> 4) * 8));
                uint32_t b0[2] = { r0, r1 }, b1[2] = { r2, r3 };
                mma16(o[nb * 2], a, b0);
                mma16(o[nb * 2 + 1], a, b1);
            }
        }
        __syncthreads();
    }

    const float invA = 1.f / lA;
    const float invB = 1.f / lB;
    const int jA = q0 + rA, jB = q0 + rB;
    if (jA < nv) {
        __half* dA = g_O16 + ((size_t)(b * Nn) + vb[jA]) * Dd + h * HDd;
#pragma unroll
        for (int jj = 0; jj < 16; jj++) {
            int c0 = jj * 8 + 2 * tg;
            *(half2*)(dA + c0) = __floats2half2_rn(o[jj][0] * invA, o[jj][1] * invA);
        }
    }
    if (jB < nv) {
        __half* dB = g_O16 + ((size_t)(b * Nn) + vb[jB]) * Dd + h * HDd;
#pragma unroll
        for (int jj = 0; jj < 16; jj++) {
            int c0 = jj * 8 + 2 * tg;
            *(half2*)(dB + c0) = __floats2half2_rn(o[jj][2] * invB, o[jj][3] * invB);
        }
    }
}

// ============================================================
// Kernel 3: out = O16 @ Wfc16 + bfc (fp32 out)
// ============================================================
__global__ __launch_bounds__(256) void fc_gemm(
    const float* __restrict__ bfc, float* __restrict__ out)
{
    extern __shared__ __half sm[];
    __half* As = sm;
    __half* Bs = sm + 2*A_ST;

    const int m0 = blockIdx.x * 128;
    const int n0 = blockIdx.y * 128;
    const int t    = threadIdx.x;
    const int lane = t & 31;
    const int warp = t >> 5;
    const int g    = lane >> 2;
    const int tg   = lane & 3;
    const int wm   = warp >> 1;
    const int wn   = warp & 1;

    float acc[2][8][4];
#pragma unroll
    for (int mt = 0; mt < 2; mt++)
#pragma unroll
        for (int nt = 0; nt < 8; nt++)
#pragma unroll
            for (int i = 0; i < 4; i++) acc[mt][nt][i] = 0.f;

    auto load_stage = [&](int k0, int st) {
        __half* Ad = As + st * A_ST;
        __half* Bd = Bs + st * B_ST;
#pragma unroll
        for (int pp = 0; pp < 4; pp++) {
            int idx = t + pp * 256;
            int r = idx >> 3, c = (idx & 7) * 8;
            CP16(smaddr(Ad + r * 72 + c), g_O16 + (size_t)(m0 + r) * Dd + k0 + c);
        }
#pragma unroll
        for (int pp = 0; pp < 4; pp++) {
            int idx = t + pp * 256;
            int r = idx >> 4, c = (idx & 15) * 8;
            CP16(smaddr(Bd + r * 136 + c), g_Wfc16 + (size_t)(k0 + r) * Dd + n0 + c);
        }
    };

    load_stage(0, 0);
    CP_COMMIT();

    for (int s = 0; s < 16; s++) {
        int cur = s & 1;
        if (s < 15) { load_stage((s + 1) * 64, cur ^ 1); CP_COMMIT(); CP_WAIT1(); }
        else        { CP_WAIT0(); }
        __syncthreads();

        const __half* Ac = As + cur * A_ST;
        const __half* Bc = Bs + cur * B_ST;
#pragma unroll
        for (int ks = 0; ks < 4; ks++) {
            int kk = ks * 16;
            uint32_t a[2][4];
#pragma unroll
            for (int mt = 0; mt < 2; mt++)
                ldsm4(a[mt][0], a[mt][1], a[mt][2], a[mt][3],
                      smaddr(Ac + (wm * 32 + mt * 16 + (lane & 15)) * 72 + kk + ((lane >> 4) << 3)));
            uint32_t bf[8][2];
#pragma unroll
            for (int nb = 0; nb < 4; nb++) {
                int nn0 = wn * 64 + nb * 16;
                uint32_t r0, r1, r2, r3;
                ldsm4t(r0, r1, r2, r3,
                       smaddr(Bc + (kk + ((lane >> 3) & 1) * 8 + (lane & 7)) * 136 + nn0 + (lane >> 4) * 8));
                bf[nb * 2][0] = r0; bf[nb * 2][1] = r1;
                bf[nb * 2 + 1][0] = r2; bf[nb * 2 + 1][1] = r3;
            }
#pragma unroll
            for (int mt = 0; mt < 2; mt++)
#pragma unroll
                for (int nt = 0; nt < 8; nt++)
                    mma16(acc[mt][nt], a[mt], bf[nt]);
        }
        __syncthreads();
    }

#pragma unroll
    for (int mt = 0; mt < 2; mt++) {
#pragma unroll
        for (int half = 0; half < 2; half++) {
            int r = m0 + wm * 32 + mt * 16 + g + half * 8;
            float* dst = out + (size_t)r * Dd + n0;
#pragma unroll
            for (int nt = 0; nt < 8; nt++) {
                int cc = wn * 64 + nt * 8 + 2 * tg;
                float2 v;
                v.x = acc[mt][nt][half * 2 + 0] + bfc[n0 + cc];
                v.y = acc[mt][nt][half * 2 + 1] + bfc[n0 + cc + 1];
                *(float2*)(dst + cc) = v;
            }
        }
    }
}

// ============================================================
extern "C" void kernel_launch(void* const* d_in, const int* in_sizes, int n_in,
                              void* d_out, int out_size)
{
    const float* x      = (const float*)d_in[0];
    const int*   x_mask = (const int*)  d_in[1];
    const float* Wq     = (const float*)d_in[2];
    const float* bq     = (const float*)d_in[3];
    const float* Wk     = (const float*)d_in[4];
    const float* bk     = (const float*)d_in[5];
    const float* Wv     = (const float*)d_in[6];
    const float* bv     = (const float*)d_in[7];
    const float* Wfc    = (const float*)d_in[8];
    const float* bfc    = (const float*)d_in[9];
    float* out = (float*)d_out;

    static bool attr_done = false;
    if (!attr_done) {
        cudaFuncSetAttribute(attn_kernel, cudaFuncAttributeMaxDynamicSharedMemorySize, ATTN_SMEM_BYTES);
        cudaFuncSetAttribute(v_gemm,  cudaFuncAttributeMaxDynamicSharedMemorySize, GEMM_SMEM);
        cudaFuncSetAttribute(qk_gemm, cudaFuncAttributeMaxDynamicSharedMemorySize, GEMM_SMEM);
        cudaFuncSetAttribute(fc_gemm, cudaFuncAttributeMaxDynamicSharedMemorySize, GEMM_SMEM);
        attr_done = true;
    }

    convert_all<<<2048, 256>>>(x, Wq, Wk, Wv, Wfc);
    build_valid<<<16, 1024>>>(x_mask);
    scan16<<<1, 32>>>();
    gather_valid<<<16, 1024>>>();
    v_gemm<<<dim3(128, 1, 8), 256, GEMM_SMEM>>>(bv);
    qk_gemm<<<dim3(128, 1, 16), 256, GEMM_SMEM>>>(bq, bk);
    vsum_kernel<<<dim3(8, 16), dim3(128, 4)>>>();
    fill_invalid<<<dim3(512, 16), 256>>>(x_mask);
    attn_kernel<<<dim3(8, 8, 16), 256, ATTN_SMEM_BYTES>>>();
    fc_gemm<<<dim3(128, 8, 1), 256, GEMM_SMEM>>>(bfc, out);
}